// round 1
// baseline (speedup 1.0000x reference)
#include <cuda_runtime.h>
#include <math.h>

#define BB   16
#define NPTS 4096
#define MPTS 1024
#define CH   256     // C1 = C2 = H1 = H2
#define LDW1 512     // w1 row stride (Cin)

// Scratch (static device globals — no runtime allocation)
__device__ int   g_idx[BB * NPTS * 3];
__device__ float g_wts[BB * NPTS * 3];
__device__ float g_G[BB * MPTS * CH];   // [b][m][o]  (W1a @ feat2, transposed)  16 MB
__device__ float g_F[BB * NPTS * CH];   // [b][n][o]  (W1b @ feat1, transposed)  64 MB
__device__ float g_H[BB * NPTS * CH];   // [b][n][o]  hidden after MLP1          64 MB

// ---------------------------------------------------------------------------
// Kernel 1: 3-NN search. One thread per query point. xyz2 tile in shared.
// ---------------------------------------------------------------------------
__global__ void knn_kernel(const float* __restrict__ xyz1,
                           const float* __restrict__ xyz2)
{
    __shared__ float s2[MPTS * 3];
    const int b   = blockIdx.y;
    const int tid = threadIdx.x;

    for (int i = tid; i < MPTS * 3; i += blockDim.x)
        s2[i] = xyz2[(size_t)b * MPTS * 3 + i];
    __syncthreads();

    const int n = blockIdx.x * blockDim.x + tid;
    const float* p = xyz1 + ((size_t)b * NPTS + n) * 3;
    const float px = p[0], py = p[1], pz = p[2];

    float d0 = 3.4e38f, d1 = 3.4e38f, d2 = 3.4e38f;
    int   i0 = 0, i1 = 0, i2 = 0;

    #pragma unroll 4
    for (int m = 0; m < MPTS; ++m) {
        const float dx = s2[3 * m + 0] - px;
        const float dy = s2[3 * m + 1] - py;
        const float dz = s2[3 * m + 2] - pz;
        const float d  = dx * dx + dy * dy + dz * dz;
        if (d < d2) {
            if (d < d0)      { d2 = d1; i2 = i1; d1 = d0; i1 = i0; d0 = d; i0 = m; }
            else if (d < d1) { d2 = d1; i2 = i1; d1 = d;  i1 = m; }
            else             { d2 = d;  i2 = m; }
        }
    }

    const float wa = 1.0f / (d0 + 1e-8f);
    const float wb = 1.0f / (d1 + 1e-8f);
    const float wc = 1.0f / (d2 + 1e-8f);
    const float ws = 1.0f / (wa + wb + wc);

    const size_t o = ((size_t)b * NPTS + n) * 3;
    g_idx[o + 0] = i0; g_idx[o + 1] = i1; g_idx[o + 2] = i2;
    g_wts[o + 0] = wa * ws; g_wts[o + 1] = wb * ws; g_wts[o + 2] = wc * ws;
}

// ---------------------------------------------------------------------------
// Kernel 2 (V1): OutT[b][n][o] = sum_k W[o][koff+k] * X[b][k][n]
// Block tile: 128 o x 128 n, K-tile 16, 256 threads, 8x8 per thread.
// X is natural [K][nn] per batch; output is TRANSPOSED [nn][256].
// ---------------------------------------------------------------------------
__global__ __launch_bounds__(256)
void gemm_v1(const float* __restrict__ W, int ldw, int koff, int K,
             const float* __restrict__ X, int nn,
             float* __restrict__ OutT)
{
    __shared__ float sW[16][132];
    __shared__ float sX[16][128];

    const int b = blockIdx.z;
    X    += (size_t)b * K * nn;
    OutT += (size_t)b * nn * CH;

    const int n0 = blockIdx.x * 128;
    const int o0 = blockIdx.y * 128;
    const int t  = threadIdx.x;
    const int tx = t & 15;        // n-frag selector
    const int ty = t >> 4;        // o-frag selector

    float acc[8][8];
    #pragma unroll
    for (int i = 0; i < 8; ++i)
        #pragma unroll
        for (int j = 0; j < 8; ++j) acc[i][j] = 0.0f;

    const int wk = t & 15;
    const int wo = t >> 4;

    for (int k0 = 0; k0 < K; k0 += 16) {
        // W tile 128(o) x 16(k): scalar loads, coalesced along k
        #pragma unroll
        for (int r = 0; r < 8; ++r)
            sW[wk][wo + r * 16] =
                W[(size_t)(o0 + wo + r * 16) * ldw + koff + k0 + wk];
        // X tile 16(k) x 128(n): float4 loads, coalesced along n
        #pragma unroll
        for (int r = 0; r < 2; ++r) {
            const int idx4 = t + r * 256;       // 0..511
            const int kk   = idx4 >> 5;         // 0..15
            const int c    = (idx4 & 31) * 4;
            *(float4*)&sX[kk][c] =
                *(const float4*)&X[(size_t)(k0 + kk) * nn + n0 + c];
        }
        __syncthreads();

        #pragma unroll
        for (int k = 0; k < 16; ++k) {
            float4 a0 = *(float4*)&sW[k][ty * 8];
            float4 a1 = *(float4*)&sW[k][ty * 8 + 4];
            float4 b0 = *(float4*)&sX[k][tx * 8];
            float4 b1 = *(float4*)&sX[k][tx * 8 + 4];
            float av[8] = {a0.x, a0.y, a0.z, a0.w, a1.x, a1.y, a1.z, a1.w};
            float bv[8] = {b0.x, b0.y, b0.z, b0.w, b1.x, b1.y, b1.z, b1.w};
            #pragma unroll
            for (int i = 0; i < 8; ++i)
                #pragma unroll
                for (int j = 0; j < 8; ++j)
                    acc[i][j] = fmaf(av[i], bv[j], acc[i][j]);
        }
        __syncthreads();
    }

    // Store transposed: OutT[n][o]; each thread writes one 32B sector per n.
    #pragma unroll
    for (int j = 0; j < 8; ++j) {
        const int n = n0 + tx * 8 + j;
        float4 v0 = make_float4(acc[0][j], acc[1][j], acc[2][j], acc[3][j]);
        float4 v1 = make_float4(acc[4][j], acc[5][j], acc[6][j], acc[7][j]);
        *(float4*)&OutT[(size_t)n * CH + o0 + ty * 8]     = v0;
        *(float4*)&OutT[(size_t)n * CH + o0 + ty * 8 + 4] = v1;
    }
}

// ---------------------------------------------------------------------------
// Kernel 3: combine. h1T[b][n][o] = relu(s1[o]*(F[b][n][o]
//                      + sum_k w_k * G[b][i_k][o]) + beta1[o])
// One warp per point; all loads/stores coalesced float4 along o.
// ---------------------------------------------------------------------------
__global__ void combine_kernel(const float* __restrict__ gamma,
                               const float* __restrict__ beta)
{
    const int b    = blockIdx.y;
    const int warp = threadIdx.x >> 5;
    const int lane = threadIdx.x & 31;
    const int n    = blockIdx.x * 8 + warp;

    const size_t pb = (size_t)b * NPTS + n;
    const int   i0 = g_idx[pb * 3 + 0];
    const int   i1 = g_idx[pb * 3 + 1];
    const int   i2 = g_idx[pb * 3 + 2];
    const float w0 = g_wts[pb * 3 + 0];
    const float w1 = g_wts[pb * 3 + 1];
    const float w2 = g_wts[pb * 3 + 2];

    const float* gr0 = g_G + ((size_t)b * MPTS + i0) * CH;
    const float* gr1 = g_G + ((size_t)b * MPTS + i1) * CH;
    const float* gr2 = g_G + ((size_t)b * MPTS + i2) * CH;
    const float* f   = g_F + pb * CH;
    float*       h   = g_H + pb * CH;

    const float inv = 1.0f / sqrtf(1.0f + 1e-5f);

    #pragma unroll
    for (int r = 0; r < 2; ++r) {
        const int o = (r * 32 + lane) * 4;
        float4 fv = *(const float4*)&f[o];
        float4 a  = *(const float4*)&gr0[o];
        float4 bq = *(const float4*)&gr1[o];
        float4 c  = *(const float4*)&gr2[o];
        float4 gm = *(const float4*)&gamma[o];
        float4 bt = *(const float4*)&beta[o];
        float4 v;
        v.x = fv.x + w0 * a.x + w1 * bq.x + w2 * c.x;
        v.y = fv.y + w0 * a.y + w1 * bq.y + w2 * c.y;
        v.z = fv.z + w0 * a.z + w1 * bq.z + w2 * c.z;
        v.w = fv.w + w0 * a.w + w1 * bq.w + w2 * c.w;
        v.x = fmaxf(fmaf(v.x, gm.x * inv, bt.x), 0.0f);
        v.y = fmaxf(fmaf(v.y, gm.y * inv, bt.y), 0.0f);
        v.z = fmaxf(fmaf(v.z, gm.z * inv, bt.z), 0.0f);
        v.w = fmaxf(fmaf(v.w, gm.w * inv, bt.w), 0.0f);
        *(float4*)&h[o] = v;
    }
}

// ---------------------------------------------------------------------------
// Kernel 4 (V2): Out[b][o][n] = relu(s2[o]*(sum_k W2[o][k]*H[b][n][k]) + b2[o])
// X operand is TRANSPOSED in memory ([n][k]); output is NATURAL [o][n].
// ---------------------------------------------------------------------------
__global__ __launch_bounds__(256)
void gemm_v2(const float* __restrict__ W, int ldw, int K,
             const float* __restrict__ XT, int nn,
             const float* __restrict__ gamma, const float* __restrict__ beta,
             float* __restrict__ Out)
{
    __shared__ float sW[16][132];
    __shared__ float sX[16][132];

    const int b = blockIdx.z;
    XT  += (size_t)b * nn * K;
    Out += (size_t)b * CH * nn;

    const int n0 = blockIdx.x * 128;
    const int o0 = blockIdx.y * 128;
    const int t  = threadIdx.x;
    const int tx = t & 15;
    const int ty = t >> 4;

    float acc[8][8];
    #pragma unroll
    for (int i = 0; i < 8; ++i)
        #pragma unroll
        for (int j = 0; j < 8; ++j) acc[i][j] = 0.0f;

    const int wk = t & 15;
    const int wo = t >> 4;

    for (int k0 = 0; k0 < K; k0 += 16) {
        #pragma unroll
        for (int r = 0; r < 8; ++r)
            sW[wk][wo + r * 16] =
                W[(size_t)(o0 + wo + r * 16) * ldw + k0 + wk];
        // X tile from XT[n][k]: float4 along k, scatter-transpose into sX[k][n]
        #pragma unroll
        for (int r = 0; r < 2; ++r) {
            const int idx4 = t + r * 256;       // 0..511
            const int ni   = idx4 >> 2;         // 0..127
            const int q    = (idx4 & 3) * 4;    // 0,4,8,12
            float4 v = *(const float4*)&XT[(size_t)(n0 + ni) * K + k0 + q];
            sX[q + 0][ni] = v.x;
            sX[q + 1][ni] = v.y;
            sX[q + 2][ni] = v.z;
            sX[q + 3][ni] = v.w;
        }
        __syncthreads();

        #pragma unroll
        for (int k = 0; k < 16; ++k) {
            float4 a0 = *(float4*)&sW[k][ty * 8];
            float4 a1 = *(float4*)&sW[k][ty * 8 + 4];
            float4 b0 = *(float4*)&sX[k][tx * 8];
            float4 b1 = *(float4*)&sX[k][tx * 8 + 4];
            float av[8] = {a0.x, a0.y, a0.z, a0.w, a1.x, a1.y, a1.z, a1.w};
            float bv[8] = {b0.x, b0.y, b0.z, b0.w, b1.x, b1.y, b1.z, b1.w};
            #pragma unroll
            for (int i = 0; i < 8; ++i)
                #pragma unroll
                for (int j = 0; j < 8; ++j)
                    acc[i][j] = fmaf(av[i], bv[j], acc[i][j]);
        }
        __syncthreads();
    }

    const float inv = 1.0f / sqrtf(1.0f + 1e-5f);
    #pragma unroll
    for (int i = 0; i < 8; ++i) {
        const int o = o0 + ty * 8 + i;
        const float s  = gamma[o] * inv;
        const float bt = beta[o];
        float4 v0 = make_float4(
            fmaxf(fmaf(acc[i][0], s, bt), 0.0f),
            fmaxf(fmaf(acc[i][1], s, bt), 0.0f),
            fmaxf(fmaf(acc[i][2], s, bt), 0.0f),
            fmaxf(fmaf(acc[i][3], s, bt), 0.0f));
        float4 v1 = make_float4(
            fmaxf(fmaf(acc[i][4], s, bt), 0.0f),
            fmaxf(fmaf(acc[i][5], s, bt), 0.0f),
            fmaxf(fmaf(acc[i][6], s, bt), 0.0f),
            fmaxf(fmaf(acc[i][7], s, bt), 0.0f));
        *(float4*)&Out[(size_t)o * nn + n0 + tx * 8]     = v0;
        *(float4*)&Out[(size_t)o * nn + n0 + tx * 8 + 4] = v1;
    }
}

// ---------------------------------------------------------------------------
extern "C" void kernel_launch(void* const* d_in, const int* in_sizes, int n_in,
                              void* d_out, int out_size)
{
    const float* xyz1   = (const float*)d_in[0];
    const float* xyz2   = (const float*)d_in[1];
    const float* feat1  = (const float*)d_in[2];
    const float* feat2  = (const float*)d_in[3];
    const float* w1     = (const float*)d_in[4];
    const float* gamma1 = (const float*)d_in[5];
    const float* beta1  = (const float*)d_in[6];
    const float* w2     = (const float*)d_in[7];
    const float* gamma2 = (const float*)d_in[8];
    const float* beta2  = (const float*)d_in[9];
    float* out = (float*)d_out;

    float* Gp; float* Fp; float* Hp;
    cudaGetSymbolAddress((void**)&Gp, g_G);
    cudaGetSymbolAddress((void**)&Fp, g_F);
    cudaGetSymbolAddress((void**)&Hp, g_H);

    // 1. kNN (writes g_idx / g_wts)
    knn_kernel<<<dim3(NPTS / 128, BB), 128>>>(xyz1, xyz2);

    // 2a. G[b][m][o] = W1[:, 0:256] @ feat2[b]        (n-dim = M = 1024)
    gemm_v1<<<dim3(MPTS / 128, 2, BB), 256>>>(w1, LDW1, 0,   CH, feat2, MPTS, Gp);

    // 2b. F[b][n][o] = W1[:, 256:512] @ feat1[b]      (n-dim = N = 4096)
    gemm_v1<<<dim3(NPTS / 128, 2, BB), 256>>>(w1, LDW1, 256, CH, feat1, NPTS, Fp);

    // 3. combine gather + BN + ReLU -> H[b][n][o]
    combine_kernel<<<dim3(NPTS / 8, BB), 256>>>(gamma1, beta1);

    // 4. Out[b][o][n] = relu(BN(W2 @ H[b]))
    gemm_v2<<<dim3(NPTS / 128, 2, BB), 256>>>(w2, CH, CH, Hp, NPTS,
                                              gamma2, beta2, out);

    (void)in_sizes; (void)n_in; (void)out_size;
}

// round 5
// speedup vs baseline: 2.0430x; 2.0430x over previous
#include <cuda_runtime.h>
#include <cuda_bf16.h>
#include <cstdint>
#include <math.h>

#define BB   16
#define NPTS 4096
#define MPTS 1024
#define CH   256     // C1 = C2 = H1 = H2
#define LDW1 512     // w1 row stride (Cin)

// ---------------------------------------------------------------------------
// Scratch (static device globals)
// ---------------------------------------------------------------------------
__device__ int            g_idx[BB * NPTS * 3];
__device__ float          g_wts[BB * NPTS * 3];
__device__ float          g_G[BB * MPTS * CH];         // [b][m][o] fp32
__device__ float          g_F[BB * NPTS * CH];         // [b][n][o] fp32
__device__ __nv_bfloat16  g_Hhi[BB * NPTS * CH];       // [b][n][k]
__device__ __nv_bfloat16  g_Hlo[BB * NPTS * CH];
__device__ __nv_bfloat16  g_X1hi[BB * NPTS * CH];      // feat1^T  [b][n][k]
__device__ __nv_bfloat16  g_X1lo[BB * NPTS * CH];
__device__ __nv_bfloat16  g_X2hi[BB * MPTS * CH];      // feat2^T  [b][m][k]
__device__ __nv_bfloat16  g_X2lo[BB * MPTS * CH];
__device__ __nv_bfloat16  g_W1ahi[CH * CH], g_W1alo[CH * CH];
__device__ __nv_bfloat16  g_W1bhi[CH * CH], g_W1blo[CH * CH];
__device__ __nv_bfloat16  g_W2hi[CH * CH],  g_W2lo[CH * CH];

// ---------------------------------------------------------------------------
// PTX helpers (sm_80-baseline features only — valid on plain sm_100)
// ---------------------------------------------------------------------------
__device__ __forceinline__ uint32_t smem_u32(const void* p) {
    uint32_t a;
    asm("{ .reg .u64 t; cvta.to.shared.u64 t, %1; cvt.u32.u64 %0, t; }"
        : "=r"(a) : "l"(p));
    return a;
}
__device__ __forceinline__ void cp_async16(uint32_t saddr, const void* g) {
    asm volatile("cp.async.cg.shared.global [%0], [%1], 16;"
                 :: "r"(saddr), "l"(g) : "memory");
}
__device__ __forceinline__ void cp_commit() {
    asm volatile("cp.async.commit_group;" ::: "memory");
}
__device__ __forceinline__ void cp_wait0() {
    asm volatile("cp.async.wait_group 0;" ::: "memory");
}
__device__ __forceinline__ void ldm_x4(uint32_t* r, uint32_t addr) {
    asm volatile("ldmatrix.sync.aligned.m8n8.x4.shared.b16 {%0,%1,%2,%3}, [%4];"
                 : "=r"(r[0]), "=r"(r[1]), "=r"(r[2]), "=r"(r[3]) : "r"(addr));
}
__device__ __forceinline__ void mma_bf16(float* d, const uint32_t* a, const uint32_t* b) {
    asm volatile(
        "mma.sync.aligned.m16n8k16.row.col.f32.bf16.bf16.f32 "
        "{%0,%1,%2,%3}, {%4,%5,%6,%7}, {%8,%9}, {%0,%1,%2,%3};"
        : "+f"(d[0]), "+f"(d[1]), "+f"(d[2]), "+f"(d[3])
        : "r"(a[0]), "r"(a[1]), "r"(a[2]), "r"(a[3]), "r"(b[0]), "r"(b[1]));
}

// ---------------------------------------------------------------------------
// Kernel 1: 3-NN search
// ---------------------------------------------------------------------------
__global__ void knn_kernel(const float* __restrict__ xyz1,
                           const float* __restrict__ xyz2)
{
    __shared__ float s2[MPTS * 3];
    const int b   = blockIdx.y;
    const int tid = threadIdx.x;

    for (int i = tid; i < MPTS * 3; i += blockDim.x)
        s2[i] = xyz2[(size_t)b * MPTS * 3 + i];
    __syncthreads();

    const int n = blockIdx.x * blockDim.x + tid;
    const float* p = xyz1 + ((size_t)b * NPTS + n) * 3;
    const float px = p[0], py = p[1], pz = p[2];

    float d0 = 3.4e38f, d1 = 3.4e38f, d2 = 3.4e38f;
    int   i0 = 0, i1 = 0, i2 = 0;

    #pragma unroll 4
    for (int m = 0; m < MPTS; ++m) {
        const float dx = s2[3 * m + 0] - px;
        const float dy = s2[3 * m + 1] - py;
        const float dz = s2[3 * m + 2] - pz;
        const float d  = dx * dx + dy * dy + dz * dz;
        if (d < d2) {
            if (d < d0)      { d2 = d1; i2 = i1; d1 = d0; i1 = i0; d0 = d; i0 = m; }
            else if (d < d1) { d2 = d1; i2 = i1; d1 = d;  i1 = m; }
            else             { d2 = d;  i2 = m; }
        }
    }

    const float wa = 1.0f / (d0 + 1e-8f);
    const float wb = 1.0f / (d1 + 1e-8f);
    const float wc = 1.0f / (d2 + 1e-8f);
    const float ws = 1.0f / (wa + wb + wc);

    const size_t o = ((size_t)b * NPTS + n) * 3;
    g_idx[o + 0] = i0; g_idx[o + 1] = i1; g_idx[o + 2] = i2;
    g_wts[o + 0] = wa * ws; g_wts[o + 1] = wb * ws; g_wts[o + 2] = wc * ws;
}

// ---------------------------------------------------------------------------
// Weight split: W[o][ldw] slice (koff..koff+255) -> hi/lo bf16 [o][256]
// ---------------------------------------------------------------------------
__global__ void split_w_kernel(const float* __restrict__ W, int ldw, int koff,
                               __nv_bfloat16* __restrict__ Whi,
                               __nv_bfloat16* __restrict__ Wlo)
{
    const int idx = blockIdx.x * blockDim.x + threadIdx.x;
    const int o = idx >> 8, k = idx & 255;
    const float v = W[(size_t)o * ldw + koff + k];
    const __nv_bfloat16 hi = __float2bfloat16(v);
    const __nv_bfloat16 lo = __float2bfloat16(v - __bfloat162float(hi));
    Whi[idx] = hi; Wlo[idx] = lo;
}

// ---------------------------------------------------------------------------
// Transpose + split: X [b][CH(k)][nn] fp32 -> Thi/Tlo [b][nn][CH] bf16
// ---------------------------------------------------------------------------
__global__ void transpose_split_kernel(const float* __restrict__ X, int nn,
                                       __nv_bfloat16* __restrict__ Thi,
                                       __nv_bfloat16* __restrict__ Tlo)
{
    __shared__ float s[32][33];
    const int b  = blockIdx.z;
    const int n0 = blockIdx.x * 32;
    const int k0 = blockIdx.y * 32;
    const int tx = threadIdx.x, ty = threadIdx.y;

    const float* Xb = X + (size_t)b * CH * nn;
    #pragma unroll
    for (int j = 0; j < 4; ++j) {
        const int kl = ty + j * 8;
        s[kl][tx] = Xb[(size_t)(k0 + kl) * nn + n0 + tx];
    }
    __syncthreads();

    __nv_bfloat16* Th = Thi + (size_t)b * nn * CH;
    __nv_bfloat16* Tl = Tlo + (size_t)b * nn * CH;
    #pragma unroll
    for (int j = 0; j < 4; ++j) {
        const int nl = ty + j * 8;
        const float v = s[tx][nl];
        const __nv_bfloat16 hi = __float2bfloat16(v);
        const __nv_bfloat16 lo = __float2bfloat16(v - __bfloat162float(hi));
        const size_t a = (size_t)(n0 + nl) * CH + k0 + tx;
        Th[a] = hi; Tl[a] = lo;
    }
}

// ---------------------------------------------------------------------------
// Combine: H = relu(bn(F + sum_k w_k * G_row)), output split bf16 hi/lo [n][k]
// ---------------------------------------------------------------------------
__global__ void combine_kernel(const float* __restrict__ gamma,
                               const float* __restrict__ beta)
{
    const int b    = blockIdx.y;
    const int warp = threadIdx.x >> 5;
    const int lane = threadIdx.x & 31;
    const int n    = blockIdx.x * 8 + warp;

    const size_t pb = (size_t)b * NPTS + n;
    const int   i0 = g_idx[pb * 3 + 0];
    const int   i1 = g_idx[pb * 3 + 1];
    const int   i2 = g_idx[pb * 3 + 2];
    const float w0 = g_wts[pb * 3 + 0];
    const float w1 = g_wts[pb * 3 + 1];
    const float w2 = g_wts[pb * 3 + 2];

    const float* gr0 = g_G + ((size_t)b * MPTS + i0) * CH;
    const float* gr1 = g_G + ((size_t)b * MPTS + i1) * CH;
    const float* gr2 = g_G + ((size_t)b * MPTS + i2) * CH;
    const float* f   = g_F + pb * CH;
    __nv_bfloat16* hh = g_Hhi + pb * CH;
    __nv_bfloat16* hl = g_Hlo + pb * CH;

    const float inv = 1.0f / sqrtf(1.0f + 1e-5f);

    #pragma unroll
    for (int r = 0; r < 2; ++r) {
        const int o = (r * 32 + lane) * 4;
        float4 fv = *(const float4*)&f[o];
        float4 a  = *(const float4*)&gr0[o];
        float4 bq = *(const float4*)&gr1[o];
        float4 c  = *(const float4*)&gr2[o];
        float4 gm = *(const float4*)&gamma[o];
        float4 bt = *(const float4*)&beta[o];
        float v[4];
        v[0] = fmaxf(fmaf(fv.x + w0*a.x + w1*bq.x + w2*c.x, gm.x*inv, bt.x), 0.0f);
        v[1] = fmaxf(fmaf(fv.y + w0*a.y + w1*bq.y + w2*c.y, gm.y*inv, bt.y), 0.0f);
        v[2] = fmaxf(fmaf(fv.z + w0*a.z + w1*bq.z + w2*c.z, gm.z*inv, bt.z), 0.0f);
        v[3] = fmaxf(fmaf(fv.w + w0*a.w + w1*bq.w + w2*c.w, gm.w*inv, bt.w), 0.0f);
        __nv_bfloat16 hi[4], lo[4];
        #pragma unroll
        for (int j = 0; j < 4; ++j) {
            hi[j] = __float2bfloat16(v[j]);
            lo[j] = __float2bfloat16(v[j] - __bfloat162float(hi[j]));
        }
        *(__nv_bfloat162*)&hh[o]     = __nv_bfloat162(hi[0], hi[1]);
        *(__nv_bfloat162*)&hh[o + 2] = __nv_bfloat162(hi[2], hi[3]);
        *(__nv_bfloat162*)&hl[o]     = __nv_bfloat162(lo[0], lo[1]);
        *(__nv_bfloat162*)&hl[o + 2] = __nv_bfloat162(lo[2], lo[3]);
    }
}

// ---------------------------------------------------------------------------
// Tensor-core GEMM via mma.sync bf16 (split hi/lo, 3 terms).
//   D[row][col] = sum_k A[row][k]*B[col][k]  (fp32 accum)
//   Block tile 128(rows) x 128(cols); 8 warps, each 32x64.
//   K staged in chunks of 32, cp.async double-buffered.
//   Smem row pitch 80B -> conflict-free ldmatrix, no swizzle.
//   Store: Out[bz*oBS + col*outLd + row]; optional fused BN+ReLU over col.
// ---------------------------------------------------------------------------
#define KTOT    256
#define KC      32
#define NCHUNK  (KTOT / KC)
#define PITCH   80
#define ARR_BYTES (128 * PITCH)          // 10240
#define STAGE_BYTES (4 * ARR_BYTES)      // 40960
#define SMEM_GEMM (2 * STAGE_BYTES)      // 81920

template<bool BNRELU>
__global__ __launch_bounds__(256, 2)
void mma_gemm(const __nv_bfloat16* __restrict__ Ahi, const __nv_bfloat16* __restrict__ Alo,
              size_t aBS,
              const __nv_bfloat16* __restrict__ Bhi, const __nv_bfloat16* __restrict__ Blo,
              size_t bBS,
              float* __restrict__ Out, size_t oBS, int outLd,
              const float* __restrict__ gamma, const float* __restrict__ beta)
{
    extern __shared__ char sm[];
    const uint32_t sb = smem_u32(sm);

    const int tid  = threadIdx.x;
    const int warp = tid >> 5;
    const int lane = tid & 31;
    const int wm   = warp & 3;           // 4 warps over rows
    const int wn   = warp >> 2;          // 2 warps over cols
    const int bz   = blockIdx.z;

    const __nv_bfloat16* srcs[4] = {
        Ahi + bz * aBS + (size_t)(blockIdx.y * 128) * KTOT,
        Alo + bz * aBS + (size_t)(blockIdx.y * 128) * KTOT,
        Bhi + bz * bBS + (size_t)(blockIdx.x * 128) * KTOT,
        Blo + bz * bBS + (size_t)(blockIdx.x * 128) * KTOT };

    // stage loader: 2048 x 16B chunks, 8 per thread
    auto load_stage = [&](int c, int sbuf) {
        const int k0 = c * KC;
        const uint32_t stage = sb + sbuf * STAGE_BYTES;
        #pragma unroll
        for (int i = 0; i < 8; ++i) {
            const int id  = tid + i * 256;
            const int arr = id >> 9;
            const int id9 = id & 511;
            const int row = id9 >> 2;
            const int g   = id9 & 3;
            cp_async16(stage + arr * ARR_BYTES + row * PITCH + g * 16,
                       srcs[arr] + (size_t)row * KTOT + k0 + g * 8);
        }
        cp_commit();
    };

    float acc[2][8][4];
    #pragma unroll
    for (int a = 0; a < 2; ++a)
        #pragma unroll
        for (int b = 0; b < 8; ++b)
            #pragma unroll
            for (int d = 0; d < 4; ++d) acc[a][b][d] = 0.0f;

    load_stage(0, 0);

    for (int c = 0; c < NCHUNK; ++c) {
        cp_wait0();
        __syncthreads();
        if (c + 1 < NCHUNK) load_stage(c + 1, (c + 1) & 1);

        const uint32_t stage = sb + (c & 1) * STAGE_BYTES;
        const uint32_t aHb = stage;
        const uint32_t aLb = stage + ARR_BYTES;
        const uint32_t bHb = stage + 2 * ARR_BYTES;
        const uint32_t bLb = stage + 3 * ARR_BYTES;

        #pragma unroll
        for (int s = 0; s < 2; ++s) {           // two k16 steps per chunk
            // A fragments (m16k16 x2 tiles, hi & lo)
            uint32_t ah[2][4], al[2][4];
            {
                const int arow = wm * 32 + (lane & 15);
                const uint32_t acol = s * 32 + ((lane >> 4) & 1) * 16;
                ldm_x4(ah[0], aHb + (arow)      * PITCH + acol);
                ldm_x4(ah[1], aHb + (arow + 16) * PITCH + acol);
                ldm_x4(al[0], aLb + (arow)      * PITCH + acol);
                ldm_x4(al[1], aLb + (arow + 16) * PITCH + acol);
            }
            #pragma unroll
            for (int nt = 0; nt < 4; ++nt) {    // n16 tiles
                uint32_t bh[4], bl[4];
                const int brow = wn * 64 + nt * 16 + ((lane >> 4) << 3) + (lane & 7);
                const uint32_t bcol = s * 32 + ((lane >> 3) & 1) * 16;
                ldm_x4(bh, bHb + brow * PITCH + bcol);
                ldm_x4(bl, bLb + brow * PITCH + bcol);
                #pragma unroll
                for (int mi = 0; mi < 2; ++mi) {
                    mma_bf16(acc[mi][2*nt],   ah[mi], bh);
                    mma_bf16(acc[mi][2*nt+1], ah[mi], bh + 2);
                    mma_bf16(acc[mi][2*nt],   ah[mi], bl);
                    mma_bf16(acc[mi][2*nt+1], ah[mi], bl + 2);
                    mma_bf16(acc[mi][2*nt],   al[mi], bh);
                    mma_bf16(acc[mi][2*nt+1], al[mi], bh + 2);
                }
            }
        }
        __syncthreads();
    }

    // Epilogue
    const float inv = 1.0f / sqrtf(1.0f + 1e-5f);
    float* outB = Out + bz * oBS;
    #pragma unroll
    for (int mi = 0; mi < 2; ++mi) {
        const int r0 = blockIdx.y * 128 + wm * 32 + mi * 16 + (lane >> 2);
        #pragma unroll
        for (int nt = 0; nt < 8; ++nt) {
            const int c0 = blockIdx.x * 128 + wn * 64 + nt * 8 + (lane & 3) * 2;
            float v0 = acc[mi][nt][0], v1 = acc[mi][nt][1];
            float v2 = acc[mi][nt][2], v3 = acc[mi][nt][3];
            if (BNRELU) {
                const float s0 = __ldg(&gamma[c0])     * inv;
                const float s1 = __ldg(&gamma[c0 + 1]) * inv;
                const float b0 = __ldg(&beta[c0]);
                const float b1 = __ldg(&beta[c0 + 1]);
                v0 = fmaxf(fmaf(v0, s0, b0), 0.0f);
                v1 = fmaxf(fmaf(v1, s1, b1), 0.0f);
                v2 = fmaxf(fmaf(v2, s0, b0), 0.0f);
                v3 = fmaxf(fmaf(v3, s1, b1), 0.0f);
            }
            outB[(size_t)c0       * outLd + r0]     = v0;
            outB[(size_t)(c0 + 1) * outLd + r0]     = v1;
            outB[(size_t)c0       * outLd + r0 + 8] = v2;
            outB[(size_t)(c0 + 1) * outLd + r0 + 8] = v3;
        }
    }
}

// ---------------------------------------------------------------------------
extern "C" void kernel_launch(void* const* d_in, const int* in_sizes, int n_in,
                              void* d_out, int out_size)
{
    const float* xyz1   = (const float*)d_in[0];
    const float* xyz2   = (const float*)d_in[1];
    const float* feat1  = (const float*)d_in[2];
    const float* feat2  = (const float*)d_in[3];
    const float* w1     = (const float*)d_in[4];
    const float* gamma1 = (const float*)d_in[5];
    const float* beta1  = (const float*)d_in[6];
    const float* w2     = (const float*)d_in[7];
    const float* gamma2 = (const float*)d_in[8];
    const float* beta2  = (const float*)d_in[9];
    float* out = (float*)d_out;

    float *Gp, *Fp;
    __nv_bfloat16 *X1h, *X1l, *X2h, *X2l, *Hh, *Hl;
    __nv_bfloat16 *W1ah, *W1al, *W1bh, *W1bl, *W2h, *W2l;
    cudaGetSymbolAddress((void**)&Gp,  g_G);
    cudaGetSymbolAddress((void**)&Fp,  g_F);
    cudaGetSymbolAddress((void**)&X1h, g_X1hi); cudaGetSymbolAddress((void**)&X1l, g_X1lo);
    cudaGetSymbolAddress((void**)&X2h, g_X2hi); cudaGetSymbolAddress((void**)&X2l, g_X2lo);
    cudaGetSymbolAddress((void**)&Hh,  g_Hhi);  cudaGetSymbolAddress((void**)&Hl,  g_Hlo);
    cudaGetSymbolAddress((void**)&W1ah, g_W1ahi); cudaGetSymbolAddress((void**)&W1al, g_W1alo);
    cudaGetSymbolAddress((void**)&W1bh, g_W1bhi); cudaGetSymbolAddress((void**)&W1bl, g_W1blo);
    cudaGetSymbolAddress((void**)&W2h,  g_W2hi);  cudaGetSymbolAddress((void**)&W2l,  g_W2lo);

    cudaFuncSetAttribute(mma_gemm<false>, cudaFuncAttributeMaxDynamicSharedMemorySize, SMEM_GEMM);
    cudaFuncSetAttribute(mma_gemm<true>,  cudaFuncAttributeMaxDynamicSharedMemorySize, SMEM_GEMM);

    // 1. kNN
    knn_kernel<<<dim3(NPTS / 128, BB), 128>>>(xyz1, xyz2);

    // 2. weight splits
    split_w_kernel<<<256, 256>>>(w1, LDW1, 0,   W1ah, W1al);
    split_w_kernel<<<256, 256>>>(w1, LDW1, 256, W1bh, W1bl);
    split_w_kernel<<<256, 256>>>(w2, CH,   0,   W2h,  W2l);

    // 3. feature transposes + split
    transpose_split_kernel<<<dim3(MPTS / 32, CH / 32, BB), dim3(32, 8)>>>(feat2, MPTS, X2h, X2l);
    transpose_split_kernel<<<dim3(NPTS / 32, CH / 32, BB), dim3(32, 8)>>>(feat1, NPTS, X1h, X1l);

    // 4. G[b][m][o] = W1a @ feat2   (rows=o from W1a, cols=m from X2)
    mma_gemm<false><<<dim3(MPTS / 128, CH / 128, BB), 256, SMEM_GEMM>>>(
        W1ah, W1al, 0, X2h, X2l, (size_t)MPTS * CH,
        Gp, (size_t)MPTS * CH, CH, nullptr, nullptr);

    // 5. F[b][n][o] = W1b @ feat1
    mma_gemm<false><<<dim3(NPTS / 128, CH / 128, BB), 256, SMEM_GEMM>>>(
        W1bh, W1bl, 0, X1h, X1l, (size_t)NPTS * CH,
        Fp, (size_t)NPTS * CH, CH, nullptr, nullptr);

    // 6. combine -> Hhi/Hlo
    combine_kernel<<<dim3(NPTS / 8, BB), 256>>>(gamma1, beta1);

    // 7. Out[b][o][n] = relu(bn(W2 @ H))  (rows=n from H, cols=o from W2)
    mma_gemm<true><<<dim3(CH / 128, NPTS / 128, BB), 256, SMEM_GEMM>>>(
        Hh, Hl, (size_t)NPTS * CH, W2h, W2l, 0,
        out, (size_t)CH * NPTS, NPTS, gamma2, beta2);

    (void)in_sizes; (void)n_in; (void)out_size;
}

// round 6
// speedup vs baseline: 2.1638x; 1.0591x over previous
#include <cuda_runtime.h>
#include <cuda_bf16.h>
#include <cstdint>
#include <math.h>

#define BB   16
#define NPTS 4096
#define MPTS 1024
#define CH   256     // C1 = C2 = H1 = H2
#define LDW1 512     // w1 row stride (Cin)

// ---------------------------------------------------------------------------
// Scratch (static device globals)
// ---------------------------------------------------------------------------
__device__ int            g_idx[BB * NPTS * 3];
__device__ float          g_wts[BB * NPTS * 3];
__device__ float          g_G[BB * MPTS * CH];         // [b][m][o] fp32
__device__ float          g_F[BB * NPTS * CH];         // [b][n][o] fp32
__device__ __nv_bfloat16  g_Hhi[BB * NPTS * CH];       // [b][n][k]
__device__ __nv_bfloat16  g_Hlo[BB * NPTS * CH];
__device__ __nv_bfloat16  g_X1hi[BB * NPTS * CH];      // feat1^T  [b][n][k]
__device__ __nv_bfloat16  g_X1lo[BB * NPTS * CH];
__device__ __nv_bfloat16  g_X2hi[BB * MPTS * CH];      // feat2^T  [b][m][k]
__device__ __nv_bfloat16  g_X2lo[BB * MPTS * CH];
__device__ __nv_bfloat16  g_W1ahi[CH * CH], g_W1alo[CH * CH];
__device__ __nv_bfloat16  g_W1bhi[CH * CH], g_W1blo[CH * CH];
__device__ __nv_bfloat16  g_W2hi[CH * CH],  g_W2lo[CH * CH];

// ---------------------------------------------------------------------------
// PTX helpers (sm_80-baseline features only — valid on plain sm_100)
// ---------------------------------------------------------------------------
__device__ __forceinline__ uint32_t smem_u32(const void* p) {
    uint32_t a;
    asm("{ .reg .u64 t; cvta.to.shared.u64 t, %1; cvt.u32.u64 %0, t; }"
        : "=r"(a) : "l"(p));
    return a;
}
__device__ __forceinline__ void cp_async16(uint32_t saddr, const void* g) {
    asm volatile("cp.async.cg.shared.global [%0], [%1], 16;"
                 :: "r"(saddr), "l"(g) : "memory");
}
__device__ __forceinline__ void cp_commit() {
    asm volatile("cp.async.commit_group;" ::: "memory");
}
__device__ __forceinline__ void cp_wait0() {
    asm volatile("cp.async.wait_group 0;" ::: "memory");
}
__device__ __forceinline__ void ldm_x4(uint32_t* r, uint32_t addr) {
    asm volatile("ldmatrix.sync.aligned.m8n8.x4.shared.b16 {%0,%1,%2,%3}, [%4];"
                 : "=r"(r[0]), "=r"(r[1]), "=r"(r[2]), "=r"(r[3]) : "r"(addr));
}
__device__ __forceinline__ void mma_bf16(float* d, const uint32_t* a, const uint32_t* b) {
    asm volatile(
        "mma.sync.aligned.m16n8k16.row.col.f32.bf16.bf16.f32 "
        "{%0,%1,%2,%3}, {%4,%5,%6,%7}, {%8,%9}, {%0,%1,%2,%3};"
        : "+f"(d[0]), "+f"(d[1]), "+f"(d[2]), "+f"(d[3])
        : "r"(a[0]), "r"(a[1]), "r"(a[2]), "r"(a[3]), "r"(b[0]), "r"(b[1]));
}

// ---------------------------------------------------------------------------
// Kernel A: merged prep — 3 weight splits + 2 feature transpose/splits.
//   Flattened grid, 256 threads/block:
//     [0, 768)              : weight splits (3 x 256 blocks)
//     [768, 768+4096)       : transpose feat2  (32 x 8 x 16)
//     [4864, 4864+16384)    : transpose feat1  (128 x 8 x 16)
// ---------------------------------------------------------------------------
#define PREP_SPLIT_BLKS  768
#define PREP_T2_BLKS     4096
#define PREP_TOTAL       (PREP_SPLIT_BLKS + PREP_T2_BLKS + 16384)

__device__ __forceinline__ void do_transpose_split(
    const float* __restrict__ Xb, int nn, int n0, int k0,
    __nv_bfloat16* __restrict__ Th, __nv_bfloat16* __restrict__ Tl,
    float s[32][33], int tx, int ty)
{
    #pragma unroll
    for (int j = 0; j < 4; ++j) {
        const int kl = ty + j * 8;
        s[kl][tx] = Xb[(size_t)(k0 + kl) * nn + n0 + tx];
    }
    __syncthreads();
    #pragma unroll
    for (int j = 0; j < 4; ++j) {
        const int nl = ty + j * 8;
        const float v = s[tx][nl];
        const __nv_bfloat16 hi = __float2bfloat16(v);
        const __nv_bfloat16 lo = __float2bfloat16(v - __bfloat162float(hi));
        const size_t a = (size_t)(n0 + nl) * CH + k0 + tx;
        Th[a] = hi; Tl[a] = lo;
    }
}

__global__ __launch_bounds__(256)
void prep_kernel(const float* __restrict__ feat1, const float* __restrict__ feat2,
                 const float* __restrict__ w1,    const float* __restrict__ w2)
{
    __shared__ float s[32][33];
    const int bid = blockIdx.x;
    const int t   = threadIdx.x;

    if (bid < PREP_SPLIT_BLKS) {
        const int which = bid >> 8;            // 0,1,2
        const int idx   = (bid & 255) * 256 + t;
        const int o = idx >> 8, k = idx & 255;
        float v;
        __nv_bfloat16 *dh, *dl;
        if (which == 0)      { v = w1[(size_t)o * LDW1 + k];       dh = g_W1ahi; dl = g_W1alo; }
        else if (which == 1) { v = w1[(size_t)o * LDW1 + 256 + k]; dh = g_W1bhi; dl = g_W1blo; }
        else                 { v = w2[(size_t)o * CH + k];         dh = g_W2hi;  dl = g_W2lo;  }
        const __nv_bfloat16 hi = __float2bfloat16(v);
        const __nv_bfloat16 lo = __float2bfloat16(v - __bfloat162float(hi));
        dh[idx] = hi; dl[idx] = lo;
    } else if (bid < PREP_SPLIT_BLKS + PREP_T2_BLKS) {
        const int local = bid - PREP_SPLIT_BLKS;
        const int n0 = (local & 31) * 32;              // MPTS/32 = 32
        const int k0 = ((local >> 5) & 7) * 32;        // CH/32 = 8
        const int b  = local >> 8;
        do_transpose_split(feat2 + (size_t)b * CH * MPTS, MPTS, n0, k0,
                           g_X2hi + (size_t)b * MPTS * CH,
                           g_X2lo + (size_t)b * MPTS * CH,
                           s, t & 31, t >> 5);
    } else {
        const int local = bid - PREP_SPLIT_BLKS - PREP_T2_BLKS;
        const int n0 = (local & 127) * 32;             // NPTS/32 = 128
        const int k0 = ((local >> 7) & 7) * 32;
        const int b  = local >> 10;
        do_transpose_split(feat1 + (size_t)b * CH * NPTS, NPTS, n0, k0,
                           g_X1hi + (size_t)b * NPTS * CH,
                           g_X1lo + (size_t)b * NPTS * CH,
                           s, t & 31, t >> 5);
    }
}

// ---------------------------------------------------------------------------
// Kernel B: 3-NN search. Staged (x,y,z,|x|^2) float4 in smem; inner iter is
// 1 LDS.128 (broadcast) + 3 FFMA + compare. |q|^2 added back to the winners.
// ---------------------------------------------------------------------------
__global__ __launch_bounds__(256)
void knn_kernel(const float* __restrict__ xyz1,
                const float* __restrict__ xyz2)
{
    __shared__ float4 s4[MPTS];
    const int b   = blockIdx.y;
    const int tid = threadIdx.x;

    for (int m = tid; m < MPTS; m += blockDim.x) {
        const float* q = xyz2 + ((size_t)b * MPTS + m) * 3;
        const float x = q[0], y = q[1], z = q[2];
        s4[m] = make_float4(x, y, z, x * x + y * y + z * z);
    }
    __syncthreads();

    const int n = blockIdx.x * blockDim.x + tid;
    const float* p = xyz1 + ((size_t)b * NPTS + n) * 3;
    const float px = p[0], py = p[1], pz = p[2];
    const float qx2 = -2.0f * px, qy2 = -2.0f * py, qz2 = -2.0f * pz;
    const float qsq = px * px + py * py + pz * pz;

    float d0 = 3.4e38f, d1 = 3.4e38f, d2 = 3.4e38f;
    int   i0 = 0, i1 = 0, i2 = 0;

    #pragma unroll 4
    for (int m = 0; m < MPTS; ++m) {
        const float4 v = s4[m];
        float d = v.w;
        d = fmaf(qx2, v.x, d);
        d = fmaf(qy2, v.y, d);
        d = fmaf(qz2, v.z, d);
        if (d < d2) {
            if (d < d0)      { d2 = d1; i2 = i1; d1 = d0; i1 = i0; d0 = d; i0 = m; }
            else if (d < d1) { d2 = d1; i2 = i1; d1 = d;  i1 = m; }
            else             { d2 = d;  i2 = m; }
        }
    }

    d0 += qsq; d1 += qsq; d2 += qsq;
    const float wa = 1.0f / (d0 + 1e-8f);
    const float wb = 1.0f / (d1 + 1e-8f);
    const float wc = 1.0f / (d2 + 1e-8f);
    const float ws = 1.0f / (wa + wb + wc);

    const size_t o = ((size_t)b * NPTS + n) * 3;
    g_idx[o + 0] = i0; g_idx[o + 1] = i1; g_idx[o + 2] = i2;
    g_wts[o + 0] = wa * ws; g_wts[o + 1] = wb * ws; g_wts[o + 2] = wc * ws;
}

// ---------------------------------------------------------------------------
// Combine: H = relu(bn(F + sum_k w_k * G_row)), output split bf16 hi/lo [n][k]
// ---------------------------------------------------------------------------
__global__ void combine_kernel(const float* __restrict__ gamma,
                               const float* __restrict__ beta)
{
    const int b    = blockIdx.y;
    const int warp = threadIdx.x >> 5;
    const int lane = threadIdx.x & 31;
    const int n    = blockIdx.x * 8 + warp;

    const size_t pb = (size_t)b * NPTS + n;
    const int   i0 = g_idx[pb * 3 + 0];
    const int   i1 = g_idx[pb * 3 + 1];
    const int   i2 = g_idx[pb * 3 + 2];
    const float w0 = g_wts[pb * 3 + 0];
    const float w1 = g_wts[pb * 3 + 1];
    const float w2 = g_wts[pb * 3 + 2];

    const float* gr0 = g_G + ((size_t)b * MPTS + i0) * CH;
    const float* gr1 = g_G + ((size_t)b * MPTS + i1) * CH;
    const float* gr2 = g_G + ((size_t)b * MPTS + i2) * CH;
    const float* f   = g_F + pb * CH;
    __nv_bfloat16* hh = g_Hhi + pb * CH;
    __nv_bfloat16* hl = g_Hlo + pb * CH;

    const float inv = 1.0f / sqrtf(1.0f + 1e-5f);

    #pragma unroll
    for (int r = 0; r < 2; ++r) {
        const int o = (r * 32 + lane) * 4;
        float4 fv = *(const float4*)&f[o];
        float4 a  = *(const float4*)&gr0[o];
        float4 bq = *(const float4*)&gr1[o];
        float4 c  = *(const float4*)&gr2[o];
        float4 gm = *(const float4*)&gamma[o];
        float4 bt = *(const float4*)&beta[o];
        float v[4];
        v[0] = fmaxf(fmaf(fv.x + w0*a.x + w1*bq.x + w2*c.x, gm.x*inv, bt.x), 0.0f);
        v[1] = fmaxf(fmaf(fv.y + w0*a.y + w1*bq.y + w2*c.y, gm.y*inv, bt.y), 0.0f);
        v[2] = fmaxf(fmaf(fv.z + w0*a.z + w1*bq.z + w2*c.z, gm.z*inv, bt.z), 0.0f);
        v[3] = fmaxf(fmaf(fv.w + w0*a.w + w1*bq.w + w2*c.w, gm.w*inv, bt.w), 0.0f);
        __nv_bfloat16 hi[4], lo[4];
        #pragma unroll
        for (int j = 0; j < 4; ++j) {
            hi[j] = __float2bfloat16(v[j]);
            lo[j] = __float2bfloat16(v[j] - __bfloat162float(hi[j]));
        }
        *(__nv_bfloat162*)&hh[o]     = __nv_bfloat162(hi[0], hi[1]);
        *(__nv_bfloat162*)&hh[o + 2] = __nv_bfloat162(hi[2], hi[3]);
        *(__nv_bfloat162*)&hl[o]     = __nv_bfloat162(lo[0], lo[1]);
        *(__nv_bfloat162*)&hl[o + 2] = __nv_bfloat162(lo[2], lo[3]);
    }
}

// ---------------------------------------------------------------------------
// Tensor-core GEMM via mma.sync bf16 (split hi/lo, 3 terms).  (unchanged)
// ---------------------------------------------------------------------------
#define KTOT    256
#define KC      32
#define NCHUNK  (KTOT / KC)
#define PITCH   80
#define ARR_BYTES (128 * PITCH)          // 10240
#define STAGE_BYTES (4 * ARR_BYTES)      // 40960
#define SMEM_GEMM (2 * STAGE_BYTES)      // 81920

template<bool BNRELU>
__global__ __launch_bounds__(256, 2)
void mma_gemm(const __nv_bfloat16* __restrict__ Ahi, const __nv_bfloat16* __restrict__ Alo,
              size_t aBS,
              const __nv_bfloat16* __restrict__ Bhi, const __nv_bfloat16* __restrict__ Blo,
              size_t bBS,
              float* __restrict__ Out, size_t oBS, int outLd,
              const float* __restrict__ gamma, const float* __restrict__ beta)
{
    extern __shared__ char sm[];
    const uint32_t sb = smem_u32(sm);

    const int tid  = threadIdx.x;
    const int warp = tid >> 5;
    const int lane = tid & 31;
    const int wm   = warp & 3;           // 4 warps over rows
    const int wn   = warp >> 2;          // 2 warps over cols
    const int bz   = blockIdx.z;

    const __nv_bfloat16* srcs[4] = {
        Ahi + bz * aBS + (size_t)(blockIdx.y * 128) * KTOT,
        Alo + bz * aBS + (size_t)(blockIdx.y * 128) * KTOT,
        Bhi + bz * bBS + (size_t)(blockIdx.x * 128) * KTOT,
        Blo + bz * bBS + (size_t)(blockIdx.x * 128) * KTOT };

    auto load_stage = [&](int c, int sbuf) {
        const int k0 = c * KC;
        const uint32_t stage = sb + sbuf * STAGE_BYTES;
        #pragma unroll
        for (int i = 0; i < 8; ++i) {
            const int id  = tid + i * 256;
            const int arr = id >> 9;
            const int id9 = id & 511;
            const int row = id9 >> 2;
            const int g   = id9 & 3;
            cp_async16(stage + arr * ARR_BYTES + row * PITCH + g * 16,
                       srcs[arr] + (size_t)row * KTOT + k0 + g * 8);
        }
        cp_commit();
    };

    float acc[2][8][4];
    #pragma unroll
    for (int a = 0; a < 2; ++a)
        #pragma unroll
        for (int b = 0; b < 8; ++b)
            #pragma unroll
            for (int d = 0; d < 4; ++d) acc[a][b][d] = 0.0f;

    load_stage(0, 0);

    for (int c = 0; c < NCHUNK; ++c) {
        cp_wait0();
        __syncthreads();
        if (c + 1 < NCHUNK) load_stage(c + 1, (c + 1) & 1);

        const uint32_t stage = sb + (c & 1) * STAGE_BYTES;
        const uint32_t aHb = stage;
        const uint32_t aLb = stage + ARR_BYTES;
        const uint32_t bHb = stage + 2 * ARR_BYTES;
        const uint32_t bLb = stage + 3 * ARR_BYTES;

        #pragma unroll
        for (int s = 0; s < 2; ++s) {
            uint32_t ah[2][4], al[2][4];
            {
                const int arow = wm * 32 + (lane & 15);
                const uint32_t acol = s * 32 + ((lane >> 4) & 1) * 16;
                ldm_x4(ah[0], aHb + (arow)      * PITCH + acol);
                ldm_x4(ah[1], aHb + (arow + 16) * PITCH + acol);
                ldm_x4(al[0], aLb + (arow)      * PITCH + acol);
                ldm_x4(al[1], aLb + (arow + 16) * PITCH + acol);
            }
            #pragma unroll
            for (int nt = 0; nt < 4; ++nt) {
                uint32_t bh[4], bl[4];
                const int brow = wn * 64 + nt * 16 + ((lane >> 4) << 3) + (lane & 7);
                const uint32_t bcol = s * 32 + ((lane >> 3) & 1) * 16;
                ldm_x4(bh, bHb + brow * PITCH + bcol);
                ldm_x4(bl, bLb + brow * PITCH + bcol);
                #pragma unroll
                for (int mi = 0; mi < 2; ++mi) {
                    mma_bf16(acc[mi][2*nt],   ah[mi], bh);
                    mma_bf16(acc[mi][2*nt+1], ah[mi], bh + 2);
                    mma_bf16(acc[mi][2*nt],   ah[mi], bl);
                    mma_bf16(acc[mi][2*nt+1], ah[mi], bl + 2);
                    mma_bf16(acc[mi][2*nt],   al[mi], bh);
                    mma_bf16(acc[mi][2*nt+1], al[mi], bh + 2);
                }
            }
        }
        __syncthreads();
    }

    const float inv = 1.0f / sqrtf(1.0f + 1e-5f);
    float* outB = Out + bz * oBS;
    #pragma unroll
    for (int mi = 0; mi < 2; ++mi) {
        const int r0 = blockIdx.y * 128 + wm * 32 + mi * 16 + (lane >> 2);
        #pragma unroll
        for (int nt = 0; nt < 8; ++nt) {
            const int c0 = blockIdx.x * 128 + wn * 64 + nt * 8 + (lane & 3) * 2;
            float v0 = acc[mi][nt][0], v1 = acc[mi][nt][1];
            float v2 = acc[mi][nt][2], v3 = acc[mi][nt][3];
            if (BNRELU) {
                const float s0 = __ldg(&gamma[c0])     * inv;
                const float s1 = __ldg(&gamma[c0 + 1]) * inv;
                const float b0 = __ldg(&beta[c0]);
                const float b1 = __ldg(&beta[c0 + 1]);
                v0 = fmaxf(fmaf(v0, s0, b0), 0.0f);
                v1 = fmaxf(fmaf(v1, s1, b1), 0.0f);
                v2 = fmaxf(fmaf(v2, s0, b0), 0.0f);
                v3 = fmaxf(fmaf(v3, s1, b1), 0.0f);
            }
            outB[(size_t)c0       * outLd + r0]     = v0;
            outB[(size_t)(c0 + 1) * outLd + r0]     = v1;
            outB[(size_t)c0       * outLd + r0 + 8] = v2;
            outB[(size_t)(c0 + 1) * outLd + r0 + 8] = v3;
        }
    }
}

// ---------------------------------------------------------------------------
extern "C" void kernel_launch(void* const* d_in, const int* in_sizes, int n_in,
                              void* d_out, int out_size)
{
    const float* xyz1   = (const float*)d_in[0];
    const float* xyz2   = (const float*)d_in[1];
    const float* feat1  = (const float*)d_in[2];
    const float* feat2  = (const float*)d_in[3];
    const float* w1     = (const float*)d_in[4];
    const float* gamma1 = (const float*)d_in[5];
    const float* beta1  = (const float*)d_in[6];
    const float* w2     = (const float*)d_in[7];
    const float* gamma2 = (const float*)d_in[8];
    const float* beta2  = (const float*)d_in[9];
    float* out = (float*)d_out;

    float *Gp, *Fp;
    __nv_bfloat16 *X1h, *X1l, *X2h, *X2l, *Hh, *Hl;
    __nv_bfloat16 *W1ah, *W1al, *W1bh, *W1bl, *W2h, *W2l;
    cudaGetSymbolAddress((void**)&Gp,  g_G);
    cudaGetSymbolAddress((void**)&Fp,  g_F);
    cudaGetSymbolAddress((void**)&X1h, g_X1hi); cudaGetSymbolAddress((void**)&X1l, g_X1lo);
    cudaGetSymbolAddress((void**)&X2h, g_X2hi); cudaGetSymbolAddress((void**)&X2l, g_X2lo);
    cudaGetSymbolAddress((void**)&Hh,  g_Hhi);  cudaGetSymbolAddress((void**)&Hl,  g_Hlo);
    cudaGetSymbolAddress((void**)&W1ah, g_W1ahi); cudaGetSymbolAddress((void**)&W1al, g_W1alo);
    cudaGetSymbolAddress((void**)&W1bh, g_W1bhi); cudaGetSymbolAddress((void**)&W1bl, g_W1blo);
    cudaGetSymbolAddress((void**)&W2h,  g_W2hi);  cudaGetSymbolAddress((void**)&W2l,  g_W2lo);

    cudaFuncSetAttribute(mma_gemm<false>, cudaFuncAttributeMaxDynamicSharedMemorySize, SMEM_GEMM);
    cudaFuncSetAttribute(mma_gemm<true>,  cudaFuncAttributeMaxDynamicSharedMemorySize, SMEM_GEMM);

    // 1. merged prep: weight splits + feature transpose/splits
    prep_kernel<<<PREP_TOTAL, 256>>>(feat1, feat2, w1, w2);

    // 2. kNN
    knn_kernel<<<dim3(NPTS / 256, BB), 256>>>(xyz1, xyz2);

    // 3. G[b][m][o] = W1a @ feat2
    mma_gemm<false><<<dim3(MPTS / 128, CH / 128, BB), 256, SMEM_GEMM>>>(
        W1ah, W1al, 0, X2h, X2l, (size_t)MPTS * CH,
        Gp, (size_t)MPTS * CH, CH, nullptr, nullptr);

    // 4. F[b][n][o] = W1b @ feat1
    mma_gemm<false><<<dim3(NPTS / 128, CH / 128, BB), 256, SMEM_GEMM>>>(
        W1bh, W1bl, 0, X1h, X1l, (size_t)NPTS * CH,
        Fp, (size_t)NPTS * CH, CH, nullptr, nullptr);

    // 5. combine -> Hhi/Hlo
    combine_kernel<<<dim3(NPTS / 8, BB), 256>>>(gamma1, beta1);

    // 6. Out[b][o][n] = relu(bn(W2 @ H))   (6th launch -> ncu -s 5 lands here)
    mma_gemm<true><<<dim3(CH / 128, NPTS / 128, BB), 256, SMEM_GEMM>>>(
        Hh, Hl, (size_t)NPTS * CH, W2h, W2l, 0,
        out, (size_t)CH * NPTS, NPTS, gamma2, beta2);

    (void)in_sizes; (void)n_in; (void)out_size;
}

// round 7
// speedup vs baseline: 2.3519x; 1.0869x over previous
#include <cuda_runtime.h>
#include <cuda_bf16.h>
#include <cstdint>
#include <math.h>

#define BB   16
#define NPTS 4096
#define MPTS 1024
#define CH   256     // C1 = C2 = H1 = H2
#define LDW1 512     // w1 row stride (Cin)

// ---------------------------------------------------------------------------
// Scratch (static device globals)
// ---------------------------------------------------------------------------
__device__ int            g_idx[BB * NPTS * 3];
__device__ float          g_wts[BB * NPTS * 3];
__device__ float          g_G[BB * MPTS * CH];         // [b][m][o] fp32
__device__ float          g_F[BB * NPTS * CH];         // [b][n][o] fp32
__device__ __nv_bfloat16  g_Hhi[BB * NPTS * CH];       // [b][n][k]
__device__ __nv_bfloat16  g_Hlo[BB * NPTS * CH];
__device__ __nv_bfloat16  g_X1hi[BB * NPTS * CH];      // feat1^T  [b][n][k]
__device__ __nv_bfloat16  g_X1lo[BB * NPTS * CH];
__device__ __nv_bfloat16  g_X2hi[BB * MPTS * CH];      // feat2^T  [b][m][k]
__device__ __nv_bfloat16  g_X2lo[BB * MPTS * CH];
__device__ __nv_bfloat16  g_W1ahi[CH * CH], g_W1alo[CH * CH];
__device__ __nv_bfloat16  g_W1bhi[CH * CH], g_W1blo[CH * CH];
__device__ __nv_bfloat16  g_W2hi[CH * CH],  g_W2lo[CH * CH];

// ---------------------------------------------------------------------------
// PTX helpers (sm_80-baseline features only — valid on plain sm_100)
// ---------------------------------------------------------------------------
__device__ __forceinline__ uint32_t smem_u32(const void* p) {
    uint32_t a;
    asm("{ .reg .u64 t; cvta.to.shared.u64 t, %1; cvt.u32.u64 %0, t; }"
        : "=r"(a) : "l"(p));
    return a;
}
__device__ __forceinline__ void cp_async16(uint32_t saddr, const void* g) {
    asm volatile("cp.async.cg.shared.global [%0], [%1], 16;"
                 :: "r"(saddr), "l"(g) : "memory");
}
__device__ __forceinline__ void cp_commit() {
    asm volatile("cp.async.commit_group;" ::: "memory");
}
__device__ __forceinline__ void cp_wait1() {
    asm volatile("cp.async.wait_group 1;" ::: "memory");
}
__device__ __forceinline__ void ldm_x4(uint32_t* r, uint32_t addr) {
    asm volatile("ldmatrix.sync.aligned.m8n8.x4.shared.b16 {%0,%1,%2,%3}, [%4];"
                 : "=r"(r[0]), "=r"(r[1]), "=r"(r[2]), "=r"(r[3]) : "r"(addr));
}
__device__ __forceinline__ void mma_bf16(float* d, const uint32_t* a, const uint32_t* b) {
    asm volatile(
        "mma.sync.aligned.m16n8k16.row.col.f32.bf16.bf16.f32 "
        "{%0,%1,%2,%3}, {%4,%5,%6,%7}, {%8,%9}, {%0,%1,%2,%3};"
        : "+f"(d[0]), "+f"(d[1]), "+f"(d[2]), "+f"(d[3])
        : "r"(a[0]), "r"(a[1]), "r"(a[2]), "r"(a[3]), "r"(b[0]), "r"(b[1]));
}

// ---------------------------------------------------------------------------
// Kernel A: merged prep — 3 weight splits + 2 feature transpose/splits.
// ---------------------------------------------------------------------------
#define PREP_SPLIT_BLKS  768
#define PREP_T2_BLKS     4096
#define PREP_TOTAL       (PREP_SPLIT_BLKS + PREP_T2_BLKS + 16384)

__device__ __forceinline__ void do_transpose_split(
    const float* __restrict__ Xb, int nn, int n0, int k0,
    __nv_bfloat16* __restrict__ Th, __nv_bfloat16* __restrict__ Tl,
    float s[32][33], int tx, int ty)
{
    #pragma unroll
    for (int j = 0; j < 4; ++j) {
        const int kl = ty + j * 8;
        s[kl][tx] = Xb[(size_t)(k0 + kl) * nn + n0 + tx];
    }
    __syncthreads();
    #pragma unroll
    for (int j = 0; j < 4; ++j) {
        const int nl = ty + j * 8;
        const float v = s[tx][nl];
        const __nv_bfloat16 hi = __float2bfloat16(v);
        const __nv_bfloat16 lo = __float2bfloat16(v - __bfloat162float(hi));
        const size_t a = (size_t)(n0 + nl) * CH + k0 + tx;
        Th[a] = hi; Tl[a] = lo;
    }
}

__global__ __launch_bounds__(256)
void prep_kernel(const float* __restrict__ feat1, const float* __restrict__ feat2,
                 const float* __restrict__ w1,    const float* __restrict__ w2)
{
    __shared__ float s[32][33];
    const int bid = blockIdx.x;
    const int t   = threadIdx.x;

    if (bid < PREP_SPLIT_BLKS) {
        const int which = bid >> 8;            // 0,1,2
        const int idx   = (bid & 255) * 256 + t;
        const int o = idx >> 8, k = idx & 255;
        float v;
        __nv_bfloat16 *dh, *dl;
        if (which == 0)      { v = w1[(size_t)o * LDW1 + k];       dh = g_W1ahi; dl = g_W1alo; }
        else if (which == 1) { v = w1[(size_t)o * LDW1 + 256 + k]; dh = g_W1bhi; dl = g_W1blo; }
        else                 { v = w2[(size_t)o * CH + k];         dh = g_W2hi;  dl = g_W2lo;  }
        const __nv_bfloat16 hi = __float2bfloat16(v);
        const __nv_bfloat16 lo = __float2bfloat16(v - __bfloat162float(hi));
        dh[idx] = hi; dl[idx] = lo;
    } else if (bid < PREP_SPLIT_BLKS + PREP_T2_BLKS) {
        const int local = bid - PREP_SPLIT_BLKS;
        const int n0 = (local & 31) * 32;              // MPTS/32 = 32
        const int k0 = ((local >> 5) & 7) * 32;        // CH/32 = 8
        const int b  = local >> 8;
        do_transpose_split(feat2 + (size_t)b * CH * MPTS, MPTS, n0, k0,
                           g_X2hi + (size_t)b * MPTS * CH,
                           g_X2lo + (size_t)b * MPTS * CH,
                           s, t & 31, t >> 5);
    } else {
        const int local = bid - PREP_SPLIT_BLKS - PREP_T2_BLKS;
        const int n0 = (local & 127) * 32;             // NPTS/32 = 128
        const int k0 = ((local >> 7) & 7) * 32;
        const int b  = local >> 10;
        do_transpose_split(feat1 + (size_t)b * CH * NPTS, NPTS, n0, k0,
                           g_X1hi + (size_t)b * NPTS * CH,
                           g_X1lo + (size_t)b * NPTS * CH,
                           s, t & 31, t >> 5);
    }
}

// ---------------------------------------------------------------------------
// Kernel B: 3-NN search.
// ---------------------------------------------------------------------------
__global__ __launch_bounds__(256)
void knn_kernel(const float* __restrict__ xyz1,
                const float* __restrict__ xyz2)
{
    __shared__ float4 s4[MPTS];
    const int b   = blockIdx.y;
    const int tid = threadIdx.x;

    for (int m = tid; m < MPTS; m += blockDim.x) {
        const float* q = xyz2 + ((size_t)b * MPTS + m) * 3;
        const float x = q[0], y = q[1], z = q[2];
        s4[m] = make_float4(x, y, z, x * x + y * y + z * z);
    }
    __syncthreads();

    const int n = blockIdx.x * blockDim.x + tid;
    const float* p = xyz1 + ((size_t)b * NPTS + n) * 3;
    const float px = p[0], py = p[1], pz = p[2];
    const float qx2 = -2.0f * px, qy2 = -2.0f * py, qz2 = -2.0f * pz;
    const float qsq = px * px + py * py + pz * pz;

    float d0 = 3.4e38f, d1 = 3.4e38f, d2 = 3.4e38f;
    int   i0 = 0, i1 = 0, i2 = 0;

    #pragma unroll 4
    for (int m = 0; m < MPTS; ++m) {
        const float4 v = s4[m];
        float d = v.w;
        d = fmaf(qx2, v.x, d);
        d = fmaf(qy2, v.y, d);
        d = fmaf(qz2, v.z, d);
        if (d < d2) {
            if (d < d0)      { d2 = d1; i2 = i1; d1 = d0; i1 = i0; d0 = d; i0 = m; }
            else if (d < d1) { d2 = d1; i2 = i1; d1 = d;  i1 = m; }
            else             { d2 = d;  i2 = m; }
        }
    }

    d0 += qsq; d1 += qsq; d2 += qsq;
    const float wa = 1.0f / (d0 + 1e-8f);
    const float wb = 1.0f / (d1 + 1e-8f);
    const float wc = 1.0f / (d2 + 1e-8f);
    const float ws = 1.0f / (wa + wb + wc);

    const size_t o = ((size_t)b * NPTS + n) * 3;
    g_idx[o + 0] = i0; g_idx[o + 1] = i1; g_idx[o + 2] = i2;
    g_wts[o + 0] = wa * ws; g_wts[o + 1] = wb * ws; g_wts[o + 2] = wc * ws;
}

// ---------------------------------------------------------------------------
// Combine: H = relu(bn(F + sum_k w_k * G_row)), output split bf16 hi/lo [n][k]
// ---------------------------------------------------------------------------
__global__ void combine_kernel(const float* __restrict__ gamma,
                               const float* __restrict__ beta)
{
    const int b    = blockIdx.y;
    const int warp = threadIdx.x >> 5;
    const int lane = threadIdx.x & 31;
    const int n    = blockIdx.x * 8 + warp;

    const size_t pb = (size_t)b * NPTS + n;
    const int   i0 = g_idx[pb * 3 + 0];
    const int   i1 = g_idx[pb * 3 + 1];
    const int   i2 = g_idx[pb * 3 + 2];
    const float w0 = g_wts[pb * 3 + 0];
    const float w1 = g_wts[pb * 3 + 1];
    const float w2 = g_wts[pb * 3 + 2];

    const float* gr0 = g_G + ((size_t)b * MPTS + i0) * CH;
    const float* gr1 = g_G + ((size_t)b * MPTS + i1) * CH;
    const float* gr2 = g_G + ((size_t)b * MPTS + i2) * CH;
    const float* f   = g_F + pb * CH;
    __nv_bfloat16* hh = g_Hhi + pb * CH;
    __nv_bfloat16* hl = g_Hlo + pb * CH;

    const float inv = 1.0f / sqrtf(1.0f + 1e-5f);

    #pragma unroll
    for (int r = 0; r < 2; ++r) {
        const int o = (r * 32 + lane) * 4;
        float4 fv = *(const float4*)&f[o];
        float4 a  = *(const float4*)&gr0[o];
        float4 bq = *(const float4*)&gr1[o];
        float4 c  = *(const float4*)&gr2[o];
        float4 gm = *(const float4*)&gamma[o];
        float4 bt = *(const float4*)&beta[o];
        float v[4];
        v[0] = fmaxf(fmaf(fv.x + w0*a.x + w1*bq.x + w2*c.x, gm.x*inv, bt.x), 0.0f);
        v[1] = fmaxf(fmaf(fv.y + w0*a.y + w1*bq.y + w2*c.y, gm.y*inv, bt.y), 0.0f);
        v[2] = fmaxf(fmaf(fv.z + w0*a.z + w1*bq.z + w2*c.z, gm.z*inv, bt.z), 0.0f);
        v[3] = fmaxf(fmaf(fv.w + w0*a.w + w1*bq.w + w2*c.w, gm.w*inv, bt.w), 0.0f);
        __nv_bfloat16 hi[4], lo[4];
        #pragma unroll
        for (int j = 0; j < 4; ++j) {
            hi[j] = __float2bfloat16(v[j]);
            lo[j] = __float2bfloat16(v[j] - __bfloat162float(hi[j]));
        }
        *(__nv_bfloat162*)&hh[o]     = __nv_bfloat162(hi[0], hi[1]);
        *(__nv_bfloat162*)&hh[o + 2] = __nv_bfloat162(hi[2], hi[3]);
        *(__nv_bfloat162*)&hl[o]     = __nv_bfloat162(lo[0], lo[1]);
        *(__nv_bfloat162*)&hl[o + 2] = __nv_bfloat162(lo[2], lo[3]);
    }
}

// ---------------------------------------------------------------------------
// Tensor-core GEMM via mma.sync bf16 (split hi/lo, 3 terms).
//   XOR-swizzled smem (64B pitch), 3-stage cp.async pipeline (wait_group 1).
//   Block tile 128(rows) x 128(cols); 8 warps, each 32x64.
// ---------------------------------------------------------------------------
#define KTOT    256
#define KC      32
#define NCHUNK  (KTOT / KC)
#define ARR_B   (128 * 64)               // 8192  (128 rows x 64B)
#define STAGE_B (4 * ARR_B)              // 32768
#define NSTAGE  3
#define SMEM_GEMM (NSTAGE * STAGE_B)     // 98304

// physical byte offset of (row, 16B-chunk) inside one array
__device__ __forceinline__ uint32_t swz(int row, int chunk) {
    return (uint32_t)(row * 64 + ((chunk ^ ((row >> 1) & 3)) << 4));
}

template<bool BNRELU>
__global__ __launch_bounds__(256, 2)
void mma_gemm(const __nv_bfloat16* __restrict__ Ahi, const __nv_bfloat16* __restrict__ Alo,
              size_t aBS,
              const __nv_bfloat16* __restrict__ Bhi, const __nv_bfloat16* __restrict__ Blo,
              size_t bBS,
              float* __restrict__ Out, size_t oBS, int outLd,
              const float* __restrict__ gamma, const float* __restrict__ beta)
{
    extern __shared__ char sm[];
    const uint32_t sb = smem_u32(sm);

    const int tid  = threadIdx.x;
    const int warp = tid >> 5;
    const int lane = tid & 31;
    const int wm   = warp & 3;           // 4 warps over rows
    const int wn   = warp >> 2;          // 2 warps over cols
    const int bz   = blockIdx.z;

    const __nv_bfloat16* srcs[4] = {
        Ahi + bz * aBS + (size_t)(blockIdx.y * 128) * KTOT,
        Alo + bz * aBS + (size_t)(blockIdx.y * 128) * KTOT,
        Bhi + bz * bBS + (size_t)(blockIdx.x * 128) * KTOT,
        Blo + bz * bBS + (size_t)(blockIdx.x * 128) * KTOT };

    // one stage = 4 arrays x 128 rows x 4 chunks(16B) = 2048 cp.asyncs; 8/thread
    auto load_stage = [&](int c) {
        const int k0 = c * KC;
        const uint32_t stage = sb + (c % NSTAGE) * STAGE_B;
        #pragma unroll
        for (int i = 0; i < 8; ++i) {
            const int id  = tid + i * 256;
            const int arr = id >> 9;
            const int id9 = id & 511;
            const int row = id9 >> 2;
            const int ch  = id9 & 3;
            cp_async16(stage + arr * ARR_B + swz(row, ch),
                       srcs[arr] + (size_t)row * KTOT + k0 + ch * 8);
        }
        cp_commit();
    };

    float acc[2][8][4];
    #pragma unroll
    for (int a = 0; a < 2; ++a)
        #pragma unroll
        for (int b = 0; b < 8; ++b)
            #pragma unroll
            for (int d = 0; d < 4; ++d) acc[a][b][d] = 0.0f;

    load_stage(0);
    load_stage(1);

    for (int c = 0; c < NCHUNK; ++c) {
        cp_wait1();                       // stage c complete; c+1 may be in flight
        __syncthreads();                  // also: all warps done with stage c-1
        if (c + 2 < NCHUNK) load_stage(c + 2);
        else                cp_commit();  // empty group keeps numbering uniform

        const uint32_t stage = sb + (c % NSTAGE) * STAGE_B;
        const uint32_t aHb = stage;
        const uint32_t aLb = stage + ARR_B;
        const uint32_t bHb = stage + 2 * ARR_B;
        const uint32_t bLb = stage + 3 * ARR_B;

        #pragma unroll
        for (int s = 0; s < 2; ++s) {     // two k16 steps per chunk
            uint32_t ah[2][4], al[2][4];
            {
                const int arow  = wm * 32 + (lane & 15);
                const int achnk = s * 2 + ((lane >> 4) & 1);
                ldm_x4(ah[0], aHb + swz(arow,      achnk));
                ldm_x4(ah[1], aHb + swz(arow + 16, achnk));
                ldm_x4(al[0], aLb + swz(arow,      achnk));
                ldm_x4(al[1], aLb + swz(arow + 16, achnk));
            }
            #pragma unroll
            for (int nt = 0; nt < 4; ++nt) {
                uint32_t bh[4], bl[4];
                const int brow  = wn * 64 + nt * 16 + ((lane >> 4) << 3) + (lane & 7);
                const int bchnk = s * 2 + ((lane >> 3) & 1);
                ldm_x4(bh, bHb + swz(brow, bchnk));
                ldm_x4(bl, bLb + swz(brow, bchnk));
                #pragma unroll
                for (int mi = 0; mi < 2; ++mi) {
                    mma_bf16(acc[mi][2*nt],   ah[mi], bh);
                    mma_bf16(acc[mi][2*nt+1], ah[mi], bh + 2);
                    mma_bf16(acc[mi][2*nt],   ah[mi], bl);
                    mma_bf16(acc[mi][2*nt+1], ah[mi], bl + 2);
                    mma_bf16(acc[mi][2*nt],   al[mi], bh);
                    mma_bf16(acc[mi][2*nt+1], al[mi], bh + 2);
                }
            }
        }
    }

    // Epilogue
    const float inv = 1.0f / sqrtf(1.0f + 1e-5f);
    float* outB = Out + bz * oBS;
    #pragma unroll
    for (int mi = 0; mi < 2; ++mi) {
        const int r0 = blockIdx.y * 128 + wm * 32 + mi * 16 + (lane >> 2);
        #pragma unroll
        for (int nt = 0; nt < 8; ++nt) {
            const int c0 = blockIdx.x * 128 + wn * 64 + nt * 8 + (lane & 3) * 2;
            float v0 = acc[mi][nt][0], v1 = acc[mi][nt][1];
            float v2 = acc[mi][nt][2], v3 = acc[mi][nt][3];
            if (BNRELU) {
                const float s0 = __ldg(&gamma[c0])     * inv;
                const float s1 = __ldg(&gamma[c0 + 1]) * inv;
                const float b0 = __ldg(&beta[c0]);
                const float b1 = __ldg(&beta[c0 + 1]);
                v0 = fmaxf(fmaf(v0, s0, b0), 0.0f);
                v1 = fmaxf(fmaf(v1, s1, b1), 0.0f);
                v2 = fmaxf(fmaf(v2, s0, b0), 0.0f);
                v3 = fmaxf(fmaf(v3, s1, b1), 0.0f);
            }
            outB[(size_t)c0       * outLd + r0]     = v0;
            outB[(size_t)(c0 + 1) * outLd + r0]     = v1;
            outB[(size_t)c0       * outLd + r0 + 8] = v2;
            outB[(size_t)(c0 + 1) * outLd + r0 + 8] = v3;
        }
    }
}

// ---------------------------------------------------------------------------
extern "C" void kernel_launch(void* const* d_in, const int* in_sizes, int n_in,
                              void* d_out, int out_size)
{
    const float* xyz1   = (const float*)d_in[0];
    const float* xyz2   = (const float*)d_in[1];
    const float* feat1  = (const float*)d_in[2];
    const float* feat2  = (const float*)d_in[3];
    const float* w1     = (const float*)d_in[4];
    const float* gamma1 = (const float*)d_in[5];
    const float* beta1  = (const float*)d_in[6];
    const float* w2     = (const float*)d_in[7];
    const float* gamma2 = (const float*)d_in[8];
    const float* beta2  = (const float*)d_in[9];
    float* out = (float*)d_out;

    float *Gp, *Fp;
    __nv_bfloat16 *X1h, *X1l, *X2h, *X2l, *Hh, *Hl;
    __nv_bfloat16 *W1ah, *W1al, *W1bh, *W1bl, *W2h, *W2l;
    cudaGetSymbolAddress((void**)&Gp,  g_G);
    cudaGetSymbolAddress((void**)&Fp,  g_F);
    cudaGetSymbolAddress((void**)&X1h, g_X1hi); cudaGetSymbolAddress((void**)&X1l, g_X1lo);
    cudaGetSymbolAddress((void**)&X2h, g_X2hi); cudaGetSymbolAddress((void**)&X2l, g_X2lo);
    cudaGetSymbolAddress((void**)&Hh,  g_Hhi);  cudaGetSymbolAddress((void**)&Hl,  g_Hlo);
    cudaGetSymbolAddress((void**)&W1ah, g_W1ahi); cudaGetSymbolAddress((void**)&W1al, g_W1alo);
    cudaGetSymbolAddress((void**)&W1bh, g_W1bhi); cudaGetSymbolAddress((void**)&W1bl, g_W1blo);
    cudaGetSymbolAddress((void**)&W2h,  g_W2hi);  cudaGetSymbolAddress((void**)&W2l,  g_W2lo);

    cudaFuncSetAttribute(mma_gemm<false>, cudaFuncAttributeMaxDynamicSharedMemorySize, SMEM_GEMM);
    cudaFuncSetAttribute(mma_gemm<true>,  cudaFuncAttributeMaxDynamicSharedMemorySize, SMEM_GEMM);

    // 1. merged prep: weight splits + feature transpose/splits
    prep_kernel<<<PREP_TOTAL, 256>>>(feat1, feat2, w1, w2);

    // 2. kNN
    knn_kernel<<<dim3(NPTS / 256, BB), 256>>>(xyz1, xyz2);

    // 3. G[b][m][o] = W1a @ feat2
    mma_gemm<false><<<dim3(MPTS / 128, CH / 128, BB), 256, SMEM_GEMM>>>(
        W1ah, W1al, 0, X2h, X2l, (size_t)MPTS * CH,
        Gp, (size_t)MPTS * CH, CH, nullptr, nullptr);

    // 4. F[b][n][o] = W1b @ feat1
    mma_gemm<false><<<dim3(NPTS / 128, CH / 128, BB), 256, SMEM_GEMM>>>(
        W1bh, W1bl, 0, X1h, X1l, (size_t)NPTS * CH,
        Fp, (size_t)NPTS * CH, CH, nullptr, nullptr);

    // 5. combine -> Hhi/Hlo
    combine_kernel<<<dim3(NPTS / 8, BB), 256>>>(gamma1, beta1);

    // 6. Out[b][o][n] = relu(bn(W2 @ H))
    mma_gemm<true><<<dim3(CH / 128, NPTS / 128, BB), 256, SMEM_GEMM>>>(
        Hh, Hl, (size_t)NPTS * CH, W2h, W2l, 0,
        out, (size_t)CH * NPTS, NPTS, gamma2, beta2);

    (void)in_sizes; (void)n_in; (void)out_size;
}

// round 8
// speedup vs baseline: 2.5043x; 1.0648x over previous
#include <cuda_runtime.h>
#include <cuda_bf16.h>
#include <cstdint>
#include <math.h>

#define BB   16
#define NPTS 4096
#define MPTS 1024
#define CH   256     // C1 = C2 = H1 = H2
#define LDW1 512     // w1 row stride (Cin)

// ---------------------------------------------------------------------------
// Scratch (static device globals)
// ---------------------------------------------------------------------------
__device__ int            g_idx[BB * NPTS * 3];
__device__ float          g_wts[BB * NPTS * 3];
__device__ float          g_G[BB * MPTS * CH];         // [b][m][o] fp32
__device__ __nv_bfloat16  g_Hhi[BB * NPTS * CH];       // [b][n][k]
__device__ __nv_bfloat16  g_Hlo[BB * NPTS * CH];
__device__ __nv_bfloat16  g_X1hi[BB * NPTS * CH];      // feat1^T  [b][n][k]
__device__ __nv_bfloat16  g_X1lo[BB * NPTS * CH];
__device__ __nv_bfloat16  g_X2hi[BB * MPTS * CH];      // feat2^T  [b][m][k]
__device__ __nv_bfloat16  g_X2lo[BB * MPTS * CH];
__device__ __nv_bfloat16  g_W1ahi[CH * CH], g_W1alo[CH * CH];
__device__ __nv_bfloat16  g_W1bhi[CH * CH], g_W1blo[CH * CH];
__device__ __nv_bfloat16  g_W2hi[CH * CH],  g_W2lo[CH * CH];

// ---------------------------------------------------------------------------
// PTX helpers (sm_80-baseline features only — valid on plain sm_100)
// ---------------------------------------------------------------------------
__device__ __forceinline__ uint32_t smem_u32(const void* p) {
    uint32_t a;
    asm("{ .reg .u64 t; cvta.to.shared.u64 t, %1; cvt.u32.u64 %0, t; }"
        : "=r"(a) : "l"(p));
    return a;
}
__device__ __forceinline__ void cp_async16(uint32_t saddr, const void* g) {
    asm volatile("cp.async.cg.shared.global [%0], [%1], 16;"
                 :: "r"(saddr), "l"(g) : "memory");
}
__device__ __forceinline__ void cp_commit() {
    asm volatile("cp.async.commit_group;" ::: "memory");
}
__device__ __forceinline__ void cp_wait1() {
    asm volatile("cp.async.wait_group 1;" ::: "memory");
}
__device__ __forceinline__ void cp_wait0() {
    asm volatile("cp.async.wait_group 0;" ::: "memory");
}
__device__ __forceinline__ void ldm_x4(uint32_t* r, uint32_t addr) {
    asm volatile("ldmatrix.sync.aligned.m8n8.x4.shared.b16 {%0,%1,%2,%3}, [%4];"
                 : "=r"(r[0]), "=r"(r[1]), "=r"(r[2]), "=r"(r[3]) : "r"(addr));
}
__device__ __forceinline__ void mma_bf16(float* d, const uint32_t* a, const uint32_t* b) {
    asm volatile(
        "mma.sync.aligned.m16n8k16.row.col.f32.bf16.bf16.f32 "
        "{%0,%1,%2,%3}, {%4,%5,%6,%7}, {%8,%9}, {%0,%1,%2,%3};"
        : "+f"(d[0]), "+f"(d[1]), "+f"(d[2]), "+f"(d[3])
        : "r"(a[0]), "r"(a[1]), "r"(a[2]), "r"(a[3]), "r"(b[0]), "r"(b[1]));
}

// ---------------------------------------------------------------------------
// Kernel A: merged prep — 3 weight splits + 2 feature transpose/splits.
// ---------------------------------------------------------------------------
#define PREP_SPLIT_BLKS  768
#define PREP_T2_BLKS     4096
#define PREP_TOTAL       (PREP_SPLIT_BLKS + PREP_T2_BLKS + 16384)

__device__ __forceinline__ void do_transpose_split(
    const float* __restrict__ Xb, int nn, int n0, int k0,
    __nv_bfloat16* __restrict__ Th, __nv_bfloat16* __restrict__ Tl,
    float s[32][33], int tx, int ty)
{
    #pragma unroll
    for (int j = 0; j < 4; ++j) {
        const int kl = ty + j * 8;
        s[kl][tx] = Xb[(size_t)(k0 + kl) * nn + n0 + tx];
    }
    __syncthreads();
    #pragma unroll
    for (int j = 0; j < 4; ++j) {
        const int nl = ty + j * 8;
        const float v = s[tx][nl];
        const __nv_bfloat16 hi = __float2bfloat16(v);
        const __nv_bfloat16 lo = __float2bfloat16(v - __bfloat162float(hi));
        const size_t a = (size_t)(n0 + nl) * CH + k0 + tx;
        Th[a] = hi; Tl[a] = lo;
    }
}

__global__ __launch_bounds__(256)
void prep_kernel(const float* __restrict__ feat1, const float* __restrict__ feat2,
                 const float* __restrict__ w1,    const float* __restrict__ w2)
{
    __shared__ float s[32][33];
    const int bid = blockIdx.x;
    const int t   = threadIdx.x;

    if (bid < PREP_SPLIT_BLKS) {
        const int which = bid >> 8;            // 0,1,2
        const int idx   = (bid & 255) * 256 + t;
        const int o = idx >> 8, k = idx & 255;
        float v;
        __nv_bfloat16 *dh, *dl;
        if (which == 0)      { v = w1[(size_t)o * LDW1 + k];       dh = g_W1ahi; dl = g_W1alo; }
        else if (which == 1) { v = w1[(size_t)o * LDW1 + 256 + k]; dh = g_W1bhi; dl = g_W1blo; }
        else                 { v = w2[(size_t)o * CH + k];         dh = g_W2hi;  dl = g_W2lo;  }
        const __nv_bfloat16 hi = __float2bfloat16(v);
        const __nv_bfloat16 lo = __float2bfloat16(v - __bfloat162float(hi));
        dh[idx] = hi; dl[idx] = lo;
    } else if (bid < PREP_SPLIT_BLKS + PREP_T2_BLKS) {
        const int local = bid - PREP_SPLIT_BLKS;
        const int n0 = (local & 31) * 32;              // MPTS/32 = 32
        const int k0 = ((local >> 5) & 7) * 32;        // CH/32 = 8
        const int b  = local >> 8;
        do_transpose_split(feat2 + (size_t)b * CH * MPTS, MPTS, n0, k0,
                           g_X2hi + (size_t)b * MPTS * CH,
                           g_X2lo + (size_t)b * MPTS * CH,
                           s, t & 31, t >> 5);
    } else {
        const int local = bid - PREP_SPLIT_BLKS - PREP_T2_BLKS;
        const int n0 = (local & 127) * 32;             // NPTS/32 = 128
        const int k0 = ((local >> 7) & 7) * 32;
        const int b  = local >> 10;
        do_transpose_split(feat1 + (size_t)b * CH * NPTS, NPTS, n0, k0,
                           g_X1hi + (size_t)b * NPTS * CH,
                           g_X1lo + (size_t)b * NPTS * CH,
                           s, t & 31, t >> 5);
    }
}

// ---------------------------------------------------------------------------
// Kernel B: 3-NN search.
// ---------------------------------------------------------------------------
__global__ __launch_bounds__(256)
void knn_kernel(const float* __restrict__ xyz1,
                const float* __restrict__ xyz2)
{
    __shared__ float4 s4[MPTS];
    const int b   = blockIdx.y;
    const int tid = threadIdx.x;

    for (int m = tid; m < MPTS; m += blockDim.x) {
        const float* q = xyz2 + ((size_t)b * MPTS + m) * 3;
        const float x = q[0], y = q[1], z = q[2];
        s4[m] = make_float4(x, y, z, x * x + y * y + z * z);
    }
    __syncthreads();

    const int n = blockIdx.x * blockDim.x + tid;
    const float* p = xyz1 + ((size_t)b * NPTS + n) * 3;
    const float px = p[0], py = p[1], pz = p[2];
    const float qx2 = -2.0f * px, qy2 = -2.0f * py, qz2 = -2.0f * pz;
    const float qsq = px * px + py * py + pz * pz;

    float d0 = 3.4e38f, d1 = 3.4e38f, d2 = 3.4e38f;
    int   i0 = 0, i1 = 0, i2 = 0;

    #pragma unroll 4
    for (int m = 0; m < MPTS; ++m) {
        const float4 v = s4[m];
        float d = v.w;
        d = fmaf(qx2, v.x, d);
        d = fmaf(qy2, v.y, d);
        d = fmaf(qz2, v.z, d);
        if (d < d2) {
            if (d < d0)      { d2 = d1; i2 = i1; d1 = d0; i1 = i0; d0 = d; i0 = m; }
            else if (d < d1) { d2 = d1; i2 = i1; d1 = d;  i1 = m; }
            else             { d2 = d;  i2 = m; }
        }
    }

    d0 += qsq; d1 += qsq; d2 += qsq;
    const float wa = 1.0f / (d0 + 1e-8f);
    const float wb = 1.0f / (d1 + 1e-8f);
    const float wc = 1.0f / (d2 + 1e-8f);
    const float ws = 1.0f / (wa + wb + wc);

    const size_t o = ((size_t)b * NPTS + n) * 3;
    g_idx[o + 0] = i0; g_idx[o + 1] = i1; g_idx[o + 2] = i2;
    g_wts[o + 0] = wa * ws; g_wts[o + 1] = wb * ws; g_wts[o + 2] = wc * ws;
}

// ---------------------------------------------------------------------------
// Tensor-core GEMM via mma.sync bf16 (split hi/lo, 3 terms).
//   XOR-swizzled smem (64B pitch), 3-stage cp.async pipeline (wait_group 1).
//   MODE 0: store fp32 Out[col*outLd + row]                  (G GEMM)
//   MODE 1: fused BN+ReLU, store fp32                        (GEMM2 -> out)
//   MODE 2: fused interpolate+BN+ReLU+split -> g_Hhi/g_Hlo   (F GEMM)
// ---------------------------------------------------------------------------
#define KTOT    256
#define KC      32
#define NCHUNK  (KTOT / KC)
#define ARR_B   (128 * 64)               // 8192  (128 rows x 64B)
#define STAGE_B (4 * ARR_B)              // 32768
#define NSTAGE  3
#define SMEM_GEMM (NSTAGE * STAGE_B)     // 98304  (>= 128*132*4 = 67584 for S)
#define SPITCH  132

__device__ __forceinline__ uint32_t swz(int row, int chunk) {
    return (uint32_t)(row * 64 + ((chunk ^ ((row >> 1) & 3)) << 4));
}

template<int MODE>
__global__ __launch_bounds__(256, 2)
void mma_gemm(const __nv_bfloat16* __restrict__ Ahi, const __nv_bfloat16* __restrict__ Alo,
              size_t aBS,
              const __nv_bfloat16* __restrict__ Bhi, const __nv_bfloat16* __restrict__ Blo,
              size_t bBS,
              float* __restrict__ Out, size_t oBS, int outLd,
              const float* __restrict__ gamma, const float* __restrict__ beta)
{
    extern __shared__ char sm[];
    const uint32_t sb = smem_u32(sm);

    const int tid  = threadIdx.x;
    const int warp = tid >> 5;
    const int lane = tid & 31;
    const int wm   = warp & 3;           // 4 warps over rows
    const int wn   = warp >> 2;          // 2 warps over cols
    const int bz   = blockIdx.z;

    const __nv_bfloat16* srcs[4] = {
        Ahi + bz * aBS + (size_t)(blockIdx.y * 128) * KTOT,
        Alo + bz * aBS + (size_t)(blockIdx.y * 128) * KTOT,
        Bhi + bz * bBS + (size_t)(blockIdx.x * 128) * KTOT,
        Blo + bz * bBS + (size_t)(blockIdx.x * 128) * KTOT };

    auto load_stage = [&](int c) {
        const int k0 = c * KC;
        const uint32_t stage = sb + (c % NSTAGE) * STAGE_B;
        #pragma unroll
        for (int i = 0; i < 8; ++i) {
            const int id  = tid + i * 256;
            const int arr = id >> 9;
            const int id9 = id & 511;
            const int row = id9 >> 2;
            const int ch  = id9 & 3;
            cp_async16(stage + arr * ARR_B + swz(row, ch),
                       srcs[arr] + (size_t)row * KTOT + k0 + ch * 8);
        }
        cp_commit();
    };

    float acc[2][8][4];
    #pragma unroll
    for (int a = 0; a < 2; ++a)
        #pragma unroll
        for (int b = 0; b < 8; ++b)
            #pragma unroll
            for (int d = 0; d < 4; ++d) acc[a][b][d] = 0.0f;

    load_stage(0);
    load_stage(1);

    for (int c = 0; c < NCHUNK; ++c) {
        cp_wait1();
        __syncthreads();
        if (c + 2 < NCHUNK) load_stage(c + 2);
        else                cp_commit();

        const uint32_t stage = sb + (c % NSTAGE) * STAGE_B;
        const uint32_t aHb = stage;
        const uint32_t aLb = stage + ARR_B;
        const uint32_t bHb = stage + 2 * ARR_B;
        const uint32_t bLb = stage + 3 * ARR_B;

        #pragma unroll
        for (int s = 0; s < 2; ++s) {
            uint32_t ah[2][4], al[2][4];
            {
                const int arow  = wm * 32 + (lane & 15);
                const int achnk = s * 2 + ((lane >> 4) & 1);
                ldm_x4(ah[0], aHb + swz(arow,      achnk));
                ldm_x4(ah[1], aHb + swz(arow + 16, achnk));
                ldm_x4(al[0], aLb + swz(arow,      achnk));
                ldm_x4(al[1], aLb + swz(arow + 16, achnk));
            }
            #pragma unroll
            for (int nt = 0; nt < 4; ++nt) {
                uint32_t bh[4], bl[4];
                const int brow  = wn * 64 + nt * 16 + ((lane >> 4) << 3) + (lane & 7);
                const int bchnk = s * 2 + ((lane >> 3) & 1);
                ldm_x4(bh, bHb + swz(brow, bchnk));
                ldm_x4(bl, bLb + swz(brow, bchnk));
                #pragma unroll
                for (int mi = 0; mi < 2; ++mi) {
                    mma_bf16(acc[mi][2*nt],   ah[mi], bh);
                    mma_bf16(acc[mi][2*nt+1], ah[mi], bh + 2);
                    mma_bf16(acc[mi][2*nt],   ah[mi], bl);
                    mma_bf16(acc[mi][2*nt+1], ah[mi], bl + 2);
                    mma_bf16(acc[mi][2*nt],   al[mi], bh);
                    mma_bf16(acc[mi][2*nt+1], al[mi], bh + 2);
                }
            }
        }
    }

    const float inv = 1.0f / sqrtf(1.0f + 1e-5f);

    if (MODE == 2) {
        // ------- fused interpolate + BN + ReLU + bf16-split epilogue -------
        cp_wait0();
        __syncthreads();                 // pipeline smem is dead; reuse as S
        float* S = (float*)sm;           // [128 n][SPITCH]
        const int n0 = blockIdx.x * 128;
        const int o0 = blockIdx.y * 128;
        const float* Gb = g_G + (size_t)bz * MPTS * CH;

        // interpolation tile into S (each warp: 16 n-rows; lane covers 4 o)
        for (int j = 0; j < 16; ++j) {
            const int nl = warp * 16 + j;
            const size_t pb = (size_t)bz * NPTS + n0 + nl;
            const int   i0 = g_idx[pb * 3 + 0];
            const int   i1 = g_idx[pb * 3 + 1];
            const int   i2 = g_idx[pb * 3 + 2];
            const float w0 = g_wts[pb * 3 + 0];
            const float w1 = g_wts[pb * 3 + 1];
            const float w2 = g_wts[pb * 3 + 2];
            const float4 a4 = *(const float4*)(Gb + (size_t)i0 * CH + o0 + 4 * lane);
            const float4 b4 = *(const float4*)(Gb + (size_t)i1 * CH + o0 + 4 * lane);
            const float4 c4 = *(const float4*)(Gb + (size_t)i2 * CH + o0 + 4 * lane);
            float4 v;
            v.x = w0 * a4.x + w1 * b4.x + w2 * c4.x;
            v.y = w0 * a4.y + w1 * b4.y + w2 * c4.y;
            v.z = w0 * a4.z + w1 * b4.z + w2 * c4.z;
            v.w = w0 * a4.w + w1 * b4.w + w2 * c4.w;
            *(float4*)&S[nl * SPITCH + 4 * lane] = v;
        }
        __syncthreads();

        // add GEMM accumulators (F) into S
        #pragma unroll
        for (int mi = 0; mi < 2; ++mi) {
            const int ol = wm * 32 + mi * 16 + (lane >> 2);
            #pragma unroll
            for (int nt = 0; nt < 8; ++nt) {
                const int cl = wn * 64 + nt * 8 + (lane & 3) * 2;
                S[cl * SPITCH + ol]           += acc[mi][nt][0];
                S[(cl + 1) * SPITCH + ol]     += acc[mi][nt][1];
                S[cl * SPITCH + ol + 8]       += acc[mi][nt][2];
                S[(cl + 1) * SPITCH + ol + 8] += acc[mi][nt][3];
            }
        }
        __syncthreads();

        // BN + ReLU + split, coalesced store to H
        const float4 gm = *(const float4*)&gamma[o0 + 4 * lane];
        const float4 bt = *(const float4*)&beta[o0 + 4 * lane];
        for (int j = 0; j < 16; ++j) {
            const int nl = warp * 16 + j;
            float4 v = *(float4*)&S[nl * SPITCH + 4 * lane];
            v.x = fmaxf(fmaf(v.x, gm.x * inv, bt.x), 0.0f);
            v.y = fmaxf(fmaf(v.y, gm.y * inv, bt.y), 0.0f);
            v.z = fmaxf(fmaf(v.z, gm.z * inv, bt.z), 0.0f);
            v.w = fmaxf(fmaf(v.w, gm.w * inv, bt.w), 0.0f);
            __nv_bfloat16 h[4], l[4];
            h[0] = __float2bfloat16(v.x); l[0] = __float2bfloat16(v.x - __bfloat162float(h[0]));
            h[1] = __float2bfloat16(v.y); l[1] = __float2bfloat16(v.y - __bfloat162float(h[1]));
            h[2] = __float2bfloat16(v.z); l[2] = __float2bfloat16(v.z - __bfloat162float(h[2]));
            h[3] = __float2bfloat16(v.w); l[3] = __float2bfloat16(v.w - __bfloat162float(h[3]));
            const size_t hb = ((size_t)bz * NPTS + n0 + nl) * CH + o0 + 4 * lane;
            *(__nv_bfloat162*)&g_Hhi[hb]     = __nv_bfloat162(h[0], h[1]);
            *(__nv_bfloat162*)&g_Hhi[hb + 2] = __nv_bfloat162(h[2], h[3]);
            *(__nv_bfloat162*)&g_Hlo[hb]     = __nv_bfloat162(l[0], l[1]);
            *(__nv_bfloat162*)&g_Hlo[hb + 2] = __nv_bfloat162(l[2], l[3]);
        }
        return;
    }

    // ----------------- plain / BN epilogues (MODE 0 / 1) -------------------
    float* outB = Out + bz * oBS;
    #pragma unroll
    for (int mi = 0; mi < 2; ++mi) {
        const int r0 = blockIdx.y * 128 + wm * 32 + mi * 16 + (lane >> 2);
        #pragma unroll
        for (int nt = 0; nt < 8; ++nt) {
            const int c0 = blockIdx.x * 128 + wn * 64 + nt * 8 + (lane & 3) * 2;
            float v0 = acc[mi][nt][0], v1 = acc[mi][nt][1];
            float v2 = acc[mi][nt][2], v3 = acc[mi][nt][3];
            if (MODE == 1) {
                const float s0 = __ldg(&gamma[c0])     * inv;
                const float s1 = __ldg(&gamma[c0 + 1]) * inv;
                const float b0 = __ldg(&beta[c0]);
                const float b1 = __ldg(&beta[c0 + 1]);
                v0 = fmaxf(fmaf(v0, s0, b0), 0.0f);
                v1 = fmaxf(fmaf(v1, s1, b1), 0.0f);
                v2 = fmaxf(fmaf(v2, s0, b0), 0.0f);
                v3 = fmaxf(fmaf(v3, s1, b1), 0.0f);
            }
            outB[(size_t)c0       * outLd + r0]     = v0;
            outB[(size_t)(c0 + 1) * outLd + r0]     = v1;
            outB[(size_t)c0       * outLd + r0 + 8] = v2;
            outB[(size_t)(c0 + 1) * outLd + r0 + 8] = v3;
        }
    }
}

// ---------------------------------------------------------------------------
extern "C" void kernel_launch(void* const* d_in, const int* in_sizes, int n_in,
                              void* d_out, int out_size)
{
    const float* xyz1   = (const float*)d_in[0];
    const float* xyz2   = (const float*)d_in[1];
    const float* feat1  = (const float*)d_in[2];
    const float* feat2  = (const float*)d_in[3];
    const float* w1     = (const float*)d_in[4];
    const float* gamma1 = (const float*)d_in[5];
    const float* beta1  = (const float*)d_in[6];
    const float* w2     = (const float*)d_in[7];
    const float* gamma2 = (const float*)d_in[8];
    const float* beta2  = (const float*)d_in[9];
    float* out = (float*)d_out;

    float *Gp;
    __nv_bfloat16 *X1h, *X1l, *X2h, *X2l, *Hh, *Hl;
    __nv_bfloat16 *W1ah, *W1al, *W1bh, *W1bl, *W2h, *W2l;
    cudaGetSymbolAddress((void**)&Gp,  g_G);
    cudaGetSymbolAddress((void**)&X1h, g_X1hi); cudaGetSymbolAddress((void**)&X1l, g_X1lo);
    cudaGetSymbolAddress((void**)&X2h, g_X2hi); cudaGetSymbolAddress((void**)&X2l, g_X2lo);
    cudaGetSymbolAddress((void**)&Hh,  g_Hhi);  cudaGetSymbolAddress((void**)&Hl,  g_Hlo);
    cudaGetSymbolAddress((void**)&W1ah, g_W1ahi); cudaGetSymbolAddress((void**)&W1al, g_W1alo);
    cudaGetSymbolAddress((void**)&W1bh, g_W1bhi); cudaGetSymbolAddress((void**)&W1bl, g_W1blo);
    cudaGetSymbolAddress((void**)&W2h,  g_W2hi);  cudaGetSymbolAddress((void**)&W2l,  g_W2lo);

    cudaFuncSetAttribute(mma_gemm<0>, cudaFuncAttributeMaxDynamicSharedMemorySize, SMEM_GEMM);
    cudaFuncSetAttribute(mma_gemm<1>, cudaFuncAttributeMaxDynamicSharedMemorySize, SMEM_GEMM);
    cudaFuncSetAttribute(mma_gemm<2>, cudaFuncAttributeMaxDynamicSharedMemorySize, SMEM_GEMM);

    // 1. merged prep: weight splits + feature transpose/splits
    prep_kernel<<<PREP_TOTAL, 256>>>(feat1, feat2, w1, w2);

    // 2. kNN
    knn_kernel<<<dim3(NPTS / 256, BB), 256>>>(xyz1, xyz2);

    // 3. G[b][m][o] = W1a @ feat2
    mma_gemm<0><<<dim3(MPTS / 128, CH / 128, BB), 256, SMEM_GEMM>>>(
        W1ah, W1al, 0, X2h, X2l, (size_t)MPTS * CH,
        Gp, (size_t)MPTS * CH, CH, nullptr, nullptr);

    // 4. F GEMM fused with interpolation/BN/ReLU/split -> g_Hhi/g_Hlo
    mma_gemm<2><<<dim3(NPTS / 128, CH / 128, BB), 256, SMEM_GEMM>>>(
        W1bh, W1bl, 0, X1h, X1l, (size_t)NPTS * CH,
        nullptr, 0, 0, gamma1, beta1);

    // 5. Out[b][o][n] = relu(bn(W2 @ H))
    mma_gemm<1><<<dim3(CH / 128, NPTS / 128, BB), 256, SMEM_GEMM>>>(
        Hh, Hl, (size_t)NPTS * CH, W2h, W2l, 0,
        out, (size_t)CH * NPTS, NPTS, gamma2, beta2);

    (void)in_sizes; (void)n_in; (void)out_size;
}

// round 9
// speedup vs baseline: 2.6690x; 1.0658x over previous
#include <cuda_runtime.h>
#include <cuda_bf16.h>
#include <cstdint>
#include <math.h>

#define BB   16
#define NPTS 4096
#define MPTS 1024
#define CH   256     // C1 = C2 = H1 = H2
#define LDW1 512     // w1 row stride (Cin)

// ---------------------------------------------------------------------------
// Scratch (static device globals)
// ---------------------------------------------------------------------------
__device__ int            g_idx[BB * NPTS * 3];
__device__ float          g_wts[BB * NPTS * 3];
__device__ float          g_G[BB * MPTS * CH];         // [b][m][o] fp32
__device__ __nv_bfloat16  g_Hhi[BB * NPTS * CH];       // [b][n][k]
__device__ __nv_bfloat16  g_Hlo[BB * NPTS * CH];
__device__ __nv_bfloat16  g_X1hi[BB * NPTS * CH];      // feat1^T  [b][n][k]
__device__ __nv_bfloat16  g_X1lo[BB * NPTS * CH];
__device__ __nv_bfloat16  g_X2hi[BB * MPTS * CH];      // feat2^T  [b][m][k]
__device__ __nv_bfloat16  g_X2lo[BB * MPTS * CH];
__device__ __nv_bfloat16  g_W1ahi[CH * CH], g_W1alo[CH * CH];
__device__ __nv_bfloat16  g_W1bhi[CH * CH], g_W1blo[CH * CH];
__device__ __nv_bfloat16  g_W2hi[CH * CH],  g_W2lo[CH * CH];

// ---------------------------------------------------------------------------
// PTX helpers (sm_80-baseline features only — valid on plain sm_100)
// ---------------------------------------------------------------------------
__device__ __forceinline__ uint32_t smem_u32(const void* p) {
    uint32_t a;
    asm("{ .reg .u64 t; cvta.to.shared.u64 t, %1; cvt.u32.u64 %0, t; }"
        : "=r"(a) : "l"(p));
    return a;
}
__device__ __forceinline__ void cp_async16(uint32_t saddr, const void* g) {
    asm volatile("cp.async.cg.shared.global [%0], [%1], 16;"
                 :: "r"(saddr), "l"(g) : "memory");
}
__device__ __forceinline__ void cp_commit() {
    asm volatile("cp.async.commit_group;" ::: "memory");
}
__device__ __forceinline__ void cp_wait1() {
    asm volatile("cp.async.wait_group 1;" ::: "memory");
}
__device__ __forceinline__ void cp_wait0() {
    asm volatile("cp.async.wait_group 0;" ::: "memory");
}
__device__ __forceinline__ void ldm_x4(uint32_t* r, uint32_t addr) {
    asm volatile("ldmatrix.sync.aligned.m8n8.x4.shared.b16 {%0,%1,%2,%3}, [%4];"
                 : "=r"(r[0]), "=r"(r[1]), "=r"(r[2]), "=r"(r[3]) : "r"(addr));
}
__device__ __forceinline__ void mma_bf16(float* d, const uint32_t* a, const uint32_t* b) {
    asm volatile(
        "mma.sync.aligned.m16n8k16.row.col.f32.bf16.bf16.f32 "
        "{%0,%1,%2,%3}, {%4,%5,%6,%7}, {%8,%9}, {%0,%1,%2,%3};"
        : "+f"(d[0]), "+f"(d[1]), "+f"(d[2]), "+f"(d[3])
        : "r"(a[0]), "r"(a[1]), "r"(a[2]), "r"(a[3]), "r"(b[0]), "r"(b[1]));
}

// ---------------------------------------------------------------------------
// Kernel A: merged prep — kNN + 3 weight splits + 2 feature transpose/splits.
//   Block ranges (knn first so its long compute-bound blocks start early):
//     [0, 256)                      : kNN (16 n-blocks x 16 batches)
//     [256, 256+768)                : weight splits
//     [1024, 1024+4096)             : transpose feat2
//     [5120, 5120+16384)            : transpose feat1
// ---------------------------------------------------------------------------
#define PREP_KNN_BLKS    256
#define PREP_SPLIT_BLKS  768
#define PREP_T2_BLKS     4096
#define PREP_TOTAL       (PREP_KNN_BLKS + PREP_SPLIT_BLKS + PREP_T2_BLKS + 16384)

__device__ __forceinline__ void do_transpose_split(
    const float* __restrict__ Xb, int nn, int n0, int k0,
    __nv_bfloat16* __restrict__ Th, __nv_bfloat16* __restrict__ Tl,
    float (*s)[33], int tx, int ty)
{
    #pragma unroll
    for (int j = 0; j < 4; ++j) {
        const int kl = ty + j * 8;
        s[kl][tx] = Xb[(size_t)(k0 + kl) * nn + n0 + tx];
    }
    __syncthreads();
    #pragma unroll
    for (int j = 0; j < 4; ++j) {
        const int nl = ty + j * 8;
        const float v = s[tx][nl];
        const __nv_bfloat16 hi = __float2bfloat16(v);
        const __nv_bfloat16 lo = __float2bfloat16(v - __bfloat162float(hi));
        const size_t a = (size_t)(n0 + nl) * CH + k0 + tx;
        Th[a] = hi; Tl[a] = lo;
    }
}

__global__ __launch_bounds__(256)
void prep_kernel(const float* __restrict__ xyz1,  const float* __restrict__ xyz2,
                 const float* __restrict__ feat1, const float* __restrict__ feat2,
                 const float* __restrict__ w1,    const float* __restrict__ w2)
{
    __shared__ char smbuf[MPTS * 16];      // 16 KB: float4[MPTS] / float[32][33]
    const int bid = blockIdx.x;
    const int t   = threadIdx.x;

    if (bid < PREP_KNN_BLKS) {
        // ---------------- kNN ----------------
        float4* s4 = (float4*)smbuf;
        const int b = bid >> 4;            // 16 batches
        const int g = bid & 15;            // 16 n-blocks of 256

        for (int m = t; m < MPTS; m += 256) {
            const float* q = xyz2 + ((size_t)b * MPTS + m) * 3;
            const float x = q[0], y = q[1], z = q[2];
            s4[m] = make_float4(x, y, z, x * x + y * y + z * z);
        }
        __syncthreads();

        const int n = g * 256 + t;
        const float* p = xyz1 + ((size_t)b * NPTS + n) * 3;
        const float px = p[0], py = p[1], pz = p[2];
        const float qx2 = -2.0f * px, qy2 = -2.0f * py, qz2 = -2.0f * pz;
        const float qsq = px * px + py * py + pz * pz;

        float d0 = 3.4e38f, d1 = 3.4e38f, d2 = 3.4e38f;
        int   i0 = 0, i1 = 0, i2 = 0;

        #pragma unroll 4
        for (int m = 0; m < MPTS; ++m) {
            const float4 v = s4[m];
            float d = v.w;
            d = fmaf(qx2, v.x, d);
            d = fmaf(qy2, v.y, d);
            d = fmaf(qz2, v.z, d);
            if (d < d2) {
                if (d < d0)      { d2 = d1; i2 = i1; d1 = d0; i1 = i0; d0 = d; i0 = m; }
                else if (d < d1) { d2 = d1; i2 = i1; d1 = d;  i1 = m; }
                else             { d2 = d;  i2 = m; }
            }
        }

        d0 += qsq; d1 += qsq; d2 += qsq;
        const float wa = 1.0f / (d0 + 1e-8f);
        const float wb = 1.0f / (d1 + 1e-8f);
        const float wc = 1.0f / (d2 + 1e-8f);
        const float ws = 1.0f / (wa + wb + wc);

        const size_t o = ((size_t)b * NPTS + n) * 3;
        g_idx[o + 0] = i0; g_idx[o + 1] = i1; g_idx[o + 2] = i2;
        g_wts[o + 0] = wa * ws; g_wts[o + 1] = wb * ws; g_wts[o + 2] = wc * ws;
        return;
    }

    float (*s)[33] = (float (*)[33])smbuf;

    if (bid < PREP_KNN_BLKS + PREP_SPLIT_BLKS) {
        const int local = bid - PREP_KNN_BLKS;
        const int which = local >> 8;          // 0,1,2
        const int idx   = (local & 255) * 256 + t;
        const int o = idx >> 8, k = idx & 255;
        float v;
        __nv_bfloat16 *dh, *dl;
        if (which == 0)      { v = w1[(size_t)o * LDW1 + k];       dh = g_W1ahi; dl = g_W1alo; }
        else if (which == 1) { v = w1[(size_t)o * LDW1 + 256 + k]; dh = g_W1bhi; dl = g_W1blo; }
        else                 { v = w2[(size_t)o * CH + k];         dh = g_W2hi;  dl = g_W2lo;  }
        const __nv_bfloat16 hi = __float2bfloat16(v);
        const __nv_bfloat16 lo = __float2bfloat16(v - __bfloat162float(hi));
        dh[idx] = hi; dl[idx] = lo;
    } else if (bid < PREP_KNN_BLKS + PREP_SPLIT_BLKS + PREP_T2_BLKS) {
        const int local = bid - PREP_KNN_BLKS - PREP_SPLIT_BLKS;
        const int n0 = (local & 31) * 32;              // MPTS/32 = 32
        const int k0 = ((local >> 5) & 7) * 32;        // CH/32 = 8
        const int b  = local >> 8;
        do_transpose_split(feat2 + (size_t)b * CH * MPTS, MPTS, n0, k0,
                           g_X2hi + (size_t)b * MPTS * CH,
                           g_X2lo + (size_t)b * MPTS * CH,
                           s, t & 31, t >> 5);
    } else {
        const int local = bid - PREP_KNN_BLKS - PREP_SPLIT_BLKS - PREP_T2_BLKS;
        const int n0 = (local & 127) * 32;             // NPTS/32 = 128
        const int k0 = ((local >> 7) & 7) * 32;
        const int b  = local >> 10;
        do_transpose_split(feat1 + (size_t)b * CH * NPTS, NPTS, n0, k0,
                           g_X1hi + (size_t)b * NPTS * CH,
                           g_X1lo + (size_t)b * NPTS * CH,
                           s, t & 31, t >> 5);
    }
}

// ---------------------------------------------------------------------------
// Tensor-core GEMM via mma.sync bf16 (split hi/lo, 3 terms).
//   XOR-swizzled smem (64B pitch), 3-stage cp.async pipeline (wait_group 1).
//   MODE 0: store fp32 Out[col*outLd + row]                  (G GEMM)
//   MODE 1: fused BN+ReLU, store fp32                        (GEMM2 -> out)
//   MODE 2: fused interpolate+BN+ReLU+split -> g_Hhi/g_Hlo   (F GEMM)
// ---------------------------------------------------------------------------
#define KTOT    256
#define KC      32
#define NCHUNK  (KTOT / KC)
#define ARR_B   (128 * 64)               // 8192  (128 rows x 64B)
#define STAGE_B (4 * ARR_B)              // 32768
#define NSTAGE  3
#define SMEM_GEMM (NSTAGE * STAGE_B)     // 98304  (>= 128*132*4 = 67584 for S)
#define SPITCH  132

__device__ __forceinline__ uint32_t swz(int row, int chunk) {
    return (uint32_t)(row * 64 + ((chunk ^ ((row >> 1) & 3)) << 4));
}

template<int MODE>
__global__ __launch_bounds__(256, 2)
void mma_gemm(const __nv_bfloat16* __restrict__ Ahi, const __nv_bfloat16* __restrict__ Alo,
              size_t aBS,
              const __nv_bfloat16* __restrict__ Bhi, const __nv_bfloat16* __restrict__ Blo,
              size_t bBS,
              float* __restrict__ Out, size_t oBS, int outLd,
              const float* __restrict__ gamma, const float* __restrict__ beta)
{
    extern __shared__ char sm[];
    const uint32_t sb = smem_u32(sm);

    const int tid  = threadIdx.x;
    const int warp = tid >> 5;
    const int lane = tid & 31;
    const int wm   = warp & 3;           // 4 warps over rows
    const int wn   = warp >> 2;          // 2 warps over cols
    const int bz   = blockIdx.z;

    const __nv_bfloat16* srcs[4] = {
        Ahi + bz * aBS + (size_t)(blockIdx.y * 128) * KTOT,
        Alo + bz * aBS + (size_t)(blockIdx.y * 128) * KTOT,
        Bhi + bz * bBS + (size_t)(blockIdx.x * 128) * KTOT,
        Blo + bz * bBS + (size_t)(blockIdx.x * 128) * KTOT };

    auto load_stage = [&](int c) {
        const int k0 = c * KC;
        const uint32_t stage = sb + (c % NSTAGE) * STAGE_B;
        #pragma unroll
        for (int i = 0; i < 8; ++i) {
            const int id  = tid + i * 256;
            const int arr = id >> 9;
            const int id9 = id & 511;
            const int row = id9 >> 2;
            const int ch  = id9 & 3;
            cp_async16(stage + arr * ARR_B + swz(row, ch),
                       srcs[arr] + (size_t)row * KTOT + k0 + ch * 8);
        }
        cp_commit();
    };

    float acc[2][8][4];
    #pragma unroll
    for (int a = 0; a < 2; ++a)
        #pragma unroll
        for (int b = 0; b < 8; ++b)
            #pragma unroll
            for (int d = 0; d < 4; ++d) acc[a][b][d] = 0.0f;

    load_stage(0);
    load_stage(1);

    for (int c = 0; c < NCHUNK; ++c) {
        cp_wait1();
        __syncthreads();
        if (c + 2 < NCHUNK) load_stage(c + 2);
        else                cp_commit();

        const uint32_t stage = sb + (c % NSTAGE) * STAGE_B;
        const uint32_t aHb = stage;
        const uint32_t aLb = stage + ARR_B;
        const uint32_t bHb = stage + 2 * ARR_B;
        const uint32_t bLb = stage + 3 * ARR_B;

        #pragma unroll
        for (int s = 0; s < 2; ++s) {
            uint32_t ah[2][4], al[2][4];
            {
                const int arow  = wm * 32 + (lane & 15);
                const int achnk = s * 2 + ((lane >> 4) & 1);
                ldm_x4(ah[0], aHb + swz(arow,      achnk));
                ldm_x4(ah[1], aHb + swz(arow + 16, achnk));
                ldm_x4(al[0], aLb + swz(arow,      achnk));
                ldm_x4(al[1], aLb + swz(arow + 16, achnk));
            }
            #pragma unroll
            for (int nt = 0; nt < 4; ++nt) {
                uint32_t bh[4], bl[4];
                const int brow  = wn * 64 + nt * 16 + ((lane >> 4) << 3) + (lane & 7);
                const int bchnk = s * 2 + ((lane >> 3) & 1);
                ldm_x4(bh, bHb + swz(brow, bchnk));
                ldm_x4(bl, bLb + swz(brow, bchnk));
                // mi-innermost: same-accumulator reuse distance = 4
                mma_bf16(acc[0][2*nt],   ah[0], bh);
                mma_bf16(acc[1][2*nt],   ah[1], bh);
                mma_bf16(acc[0][2*nt+1], ah[0], bh + 2);
                mma_bf16(acc[1][2*nt+1], ah[1], bh + 2);
                mma_bf16(acc[0][2*nt],   ah[0], bl);
                mma_bf16(acc[1][2*nt],   ah[1], bl);
                mma_bf16(acc[0][2*nt+1], ah[0], bl + 2);
                mma_bf16(acc[1][2*nt+1], ah[1], bl + 2);
                mma_bf16(acc[0][2*nt],   al[0], bh);
                mma_bf16(acc[1][2*nt],   al[1], bh);
                mma_bf16(acc[0][2*nt+1], al[0], bh + 2);
                mma_bf16(acc[1][2*nt+1], al[1], bh + 2);
            }
        }
    }

    const float inv = 1.0f / sqrtf(1.0f + 1e-5f);

    if (MODE == 2) {
        // ------- fused interpolate + BN + ReLU + bf16-split epilogue -------
        cp_wait0();
        __syncthreads();                 // pipeline smem is dead; reuse as S
        float* S = (float*)sm;           // [128 n][SPITCH]
        const int n0 = blockIdx.x * 128;
        const int o0 = blockIdx.y * 128;
        const float* Gb = g_G + (size_t)bz * MPTS * CH;

        for (int j = 0; j < 16; ++j) {
            const int nl = warp * 16 + j;
            const size_t pb = (size_t)bz * NPTS + n0 + nl;
            const int   i0 = g_idx[pb * 3 + 0];
            const int   i1 = g_idx[pb * 3 + 1];
            const int   i2 = g_idx[pb * 3 + 2];
            const float w0 = g_wts[pb * 3 + 0];
            const float w1 = g_wts[pb * 3 + 1];
            const float w2 = g_wts[pb * 3 + 2];
            const float4 a4 = *(const float4*)(Gb + (size_t)i0 * CH + o0 + 4 * lane);
            const float4 b4 = *(const float4*)(Gb + (size_t)i1 * CH + o0 + 4 * lane);
            const float4 c4 = *(const float4*)(Gb + (size_t)i2 * CH + o0 + 4 * lane);
            float4 v;
            v.x = w0 * a4.x + w1 * b4.x + w2 * c4.x;
            v.y = w0 * a4.y + w1 * b4.y + w2 * c4.y;
            v.z = w0 * a4.z + w1 * b4.z + w2 * c4.z;
            v.w = w0 * a4.w + w1 * b4.w + w2 * c4.w;
            *(float4*)&S[nl * SPITCH + 4 * lane] = v;
        }
        __syncthreads();

        #pragma unroll
        for (int mi = 0; mi < 2; ++mi) {
            const int ol = wm * 32 + mi * 16 + (lane >> 2);
            #pragma unroll
            for (int nt = 0; nt < 8; ++nt) {
                const int cl = wn * 64 + nt * 8 + (lane & 3) * 2;
                S[cl * SPITCH + ol]           += acc[mi][nt][0];
                S[(cl + 1) * SPITCH + ol]     += acc[mi][nt][1];
                S[cl * SPITCH + ol + 8]       += acc[mi][nt][2];
                S[(cl + 1) * SPITCH + ol + 8] += acc[mi][nt][3];
            }
        }
        __syncthreads();

        const float4 gm = *(const float4*)&gamma[o0 + 4 * lane];
        const float4 bt = *(const float4*)&beta[o0 + 4 * lane];
        for (int j = 0; j < 16; ++j) {
            const int nl = warp * 16 + j;
            float4 v = *(float4*)&S[nl * SPITCH + 4 * lane];
            v.x = fmaxf(fmaf(v.x, gm.x * inv, bt.x), 0.0f);
            v.y = fmaxf(fmaf(v.y, gm.y * inv, bt.y), 0.0f);
            v.z = fmaxf(fmaf(v.z, gm.z * inv, bt.z), 0.0f);
            v.w = fmaxf(fmaf(v.w, gm.w * inv, bt.w), 0.0f);
            __nv_bfloat16 h[4], l[4];
            h[0] = __float2bfloat16(v.x); l[0] = __float2bfloat16(v.x - __bfloat162float(h[0]));
            h[1] = __float2bfloat16(v.y); l[1] = __float2bfloat16(v.y - __bfloat162float(h[1]));
            h[2] = __float2bfloat16(v.z); l[2] = __float2bfloat16(v.z - __bfloat162float(h[2]));
            h[3] = __float2bfloat16(v.w); l[3] = __float2bfloat16(v.w - __bfloat162float(h[3]));
            const size_t hb = ((size_t)bz * NPTS + n0 + nl) * CH + o0 + 4 * lane;
            *(__nv_bfloat162*)&g_Hhi[hb]     = __nv_bfloat162(h[0], h[1]);
            *(__nv_bfloat162*)&g_Hhi[hb + 2] = __nv_bfloat162(h[2], h[3]);
            *(__nv_bfloat162*)&g_Hlo[hb]     = __nv_bfloat162(l[0], l[1]);
            *(__nv_bfloat162*)&g_Hlo[hb + 2] = __nv_bfloat162(l[2], l[3]);
        }
        return;
    }

    // ----------------- plain / BN epilogues (MODE 0 / 1) -------------------
    float* outB = Out + bz * oBS;
    #pragma unroll
    for (int mi = 0; mi < 2; ++mi) {
        const int r0 = blockIdx.y * 128 + wm * 32 + mi * 16 + (lane >> 2);
        #pragma unroll
        for (int nt = 0; nt < 8; ++nt) {
            const int c0 = blockIdx.x * 128 + wn * 64 + nt * 8 + (lane & 3) * 2;
            float v0 = acc[mi][nt][0], v1 = acc[mi][nt][1];
            float v2 = acc[mi][nt][2], v3 = acc[mi][nt][3];
            if (MODE == 1) {
                const float s0 = __ldg(&gamma[c0])     * inv;
                const float s1 = __ldg(&gamma[c0 + 1]) * inv;
                const float b0 = __ldg(&beta[c0]);
                const float b1 = __ldg(&beta[c0 + 1]);
                v0 = fmaxf(fmaf(v0, s0, b0), 0.0f);
                v1 = fmaxf(fmaf(v1, s1, b1), 0.0f);
                v2 = fmaxf(fmaf(v2, s0, b0), 0.0f);
                v3 = fmaxf(fmaf(v3, s1, b1), 0.0f);
            }
            outB[(size_t)c0       * outLd + r0]     = v0;
            outB[(size_t)(c0 + 1) * outLd + r0]     = v1;
            outB[(size_t)c0       * outLd + r0 + 8] = v2;
            outB[(size_t)(c0 + 1) * outLd + r0 + 8] = v3;
        }
    }
}

// ---------------------------------------------------------------------------
extern "C" void kernel_launch(void* const* d_in, const int* in_sizes, int n_in,
                              void* d_out, int out_size)
{
    const float* xyz1   = (const float*)d_in[0];
    const float* xyz2   = (const float*)d_in[1];
    const float* feat1  = (const float*)d_in[2];
    const float* feat2  = (const float*)d_in[3];
    const float* w1     = (const float*)d_in[4];
    const float* gamma1 = (const float*)d_in[5];
    const float* beta1  = (const float*)d_in[6];
    const float* w2     = (const float*)d_in[7];
    const float* gamma2 = (const float*)d_in[8];
    const float* beta2  = (const float*)d_in[9];
    float* out = (float*)d_out;

    float *Gp;
    __nv_bfloat16 *X1h, *X1l, *X2h, *X2l, *Hh, *Hl;
    __nv_bfloat16 *W1ah, *W1al, *W1bh, *W1bl, *W2h, *W2l;
    cudaGetSymbolAddress((void**)&Gp,  g_G);
    cudaGetSymbolAddress((void**)&X1h, g_X1hi); cudaGetSymbolAddress((void**)&X1l, g_X1lo);
    cudaGetSymbolAddress((void**)&X2h, g_X2hi); cudaGetSymbolAddress((void**)&X2l, g_X2lo);
    cudaGetSymbolAddress((void**)&Hh,  g_Hhi);  cudaGetSymbolAddress((void**)&Hl,  g_Hlo);
    cudaGetSymbolAddress((void**)&W1ah, g_W1ahi); cudaGetSymbolAddress((void**)&W1al, g_W1alo);
    cudaGetSymbolAddress((void**)&W1bh, g_W1bhi); cudaGetSymbolAddress((void**)&W1bl, g_W1blo);
    cudaGetSymbolAddress((void**)&W2h,  g_W2hi);  cudaGetSymbolAddress((void**)&W2l,  g_W2lo);

    cudaFuncSetAttribute(mma_gemm<0>, cudaFuncAttributeMaxDynamicSharedMemorySize, SMEM_GEMM);
    cudaFuncSetAttribute(mma_gemm<1>, cudaFuncAttributeMaxDynamicSharedMemorySize, SMEM_GEMM);
    cudaFuncSetAttribute(mma_gemm<2>, cudaFuncAttributeMaxDynamicSharedMemorySize, SMEM_GEMM);

    // 1. merged prep: kNN + weight splits + feature transpose/splits
    prep_kernel<<<PREP_TOTAL, 256>>>(xyz1, xyz2, feat1, feat2, w1, w2);

    // 2. G[b][m][o] = W1a @ feat2
    mma_gemm<0><<<dim3(MPTS / 128, CH / 128, BB), 256, SMEM_GEMM>>>(
        W1ah, W1al, 0, X2h, X2l, (size_t)MPTS * CH,
        Gp, (size_t)MPTS * CH, CH, nullptr, nullptr);

    // 3. F GEMM fused with interpolation/BN/ReLU/split -> g_Hhi/g_Hlo
    mma_gemm<2><<<dim3(NPTS / 128, CH / 128, BB), 256, SMEM_GEMM>>>(
        W1bh, W1bl, 0, X1h, X1l, (size_t)NPTS * CH,
        nullptr, 0, 0, gamma1, beta1);

    // 4. Out[b][o][n] = relu(bn(W2 @ H))
    mma_gemm<1><<<dim3(CH / 128, NPTS / 128, BB), 256, SMEM_GEMM>>>(
        Hh, Hl, (size_t)NPTS * CH, W2h, W2l, 0,
        out, (size_t)CH * NPTS, NPTS, gamma2, beta2);

    (void)in_sizes; (void)n_in; (void)out_size;
}